// round 1
// baseline (speedup 1.0000x reference)
#include <cuda_runtime.h>
#include <math.h>

// Problem constants (from reference): N=50000, E=800000, dims 128/128/128/64.
#define MAXN 50000
#define MAXE 800000

// ---------------- scratch (device globals; no cudaMalloc allowed) ----------------
__device__ float g_t[MAXN * 128];      // GEMM output (pre-aggregation)
__device__ float g_h[MAXN * 128];      // layer activations
__device__ float g_dis[MAXN];          // rsqrt(deg)
__device__ int   g_deg[MAXN];          // in-degree counts (excl self loop)
__device__ int   g_off[MAXN + 1];      // CSR offsets
__device__ int   g_cur[MAXN];          // fill cursors
__device__ int   g_csrc[MAXE];         // CSR src indices (grouped by dst)
__device__ float g_cw[MAXE];           // CSR edge norm weights
__device__ float g_a[MAXN];            // attention logits / exp values
__device__ float g_red[8192];          // block partials
__device__ float g_scalar[2];          // [0]=max, [1]=sum

// ---------------- degree / CSR build ----------------
__global__ void zero_kernel(int n) {
    int i = blockIdx.x * blockDim.x + threadIdx.x;
    if (i < n) { g_deg[i] = 0; g_cur[i] = 0; }
}

__global__ void count_kernel(const int* __restrict__ dst, int e) {
    int i = blockIdx.x * blockDim.x + threadIdx.x;
    if (i < e) atomicAdd(&g_deg[dst[i]], 1);
}

// 1 block, 1024 threads: exclusive scan of g_deg -> g_off, and dis = rsqrt(deg+1)
__global__ void scan_kernel(int n, int e) {
    __shared__ int s[1024];
    int t = threadIdx.x;
    int chunk = (n + 1023) >> 10;
    int b = t * chunk;
    int hi = min(b + chunk, n);
    int sum = 0;
    for (int i = b; i < hi; i++) sum += g_deg[i];
    s[t] = sum;
    __syncthreads();
    // Hillis-Steele inclusive scan
    for (int off = 1; off < 1024; off <<= 1) {
        int v = (t >= off) ? s[t - off] : 0;
        __syncthreads();
        s[t] += v;
        __syncthreads();
    }
    int prefix = s[t] - sum;  // exclusive
    for (int i = b; i < hi; i++) {
        g_off[i] = prefix;
        prefix += g_deg[i];
        g_dis[i] = rsqrtf((float)g_deg[i] + 1.0f);
    }
    if (t == 1023) g_off[n] = e;
}

__global__ void fill_kernel(const int* __restrict__ src, const int* __restrict__ dst, int e) {
    int i = blockIdx.x * blockDim.x + threadIdx.x;
    if (i >= e) return;
    int d = dst[i], s = src[i];
    int p = g_off[d] + atomicAdd(&g_cur[d], 1);
    g_csrc[p] = s;
    g_cw[p] = g_dis[s] * g_dis[d];
}

// ---------------- fp32 register-blocked GEMM: T[n,OUT] = A[n,IN] @ W[IN,OUT] ----------------
template <int IN, int OUT, int BM>
__global__ __launch_bounds__(256) void gemm_kernel(const float* __restrict__ A,
                                                   const float* __restrict__ W,
                                                   float* __restrict__ T, int n) {
    constexpr int BK = 16, TM = 8, TN = 4;
    constexpr int CT = OUT / TN;   // column threads (32 or 16)
    constexpr int RT = 256 / CT;   // row threads (8 or 16)
    static_assert(RT * TM == BM, "tile config");
    __shared__ float As[BK][BM + 4];
    __shared__ float Ws[BK][OUT];

    int t = threadIdx.x;
    int m0 = blockIdx.x * BM;
    int ctid = t % CT;
    int rtid = t / CT;

    float acc[TM][TN];
#pragma unroll
    for (int i = 0; i < TM; i++)
#pragma unroll
        for (int j = 0; j < TN; j++) acc[i][j] = 0.f;

    constexpr int ALD = (BM * BK) / (4 * 256);  // float4 A loads per thread
    constexpr int WLD = (BK * OUT) / (4 * 256); // float4 W loads per thread

    for (int k0 = 0; k0 < IN; k0 += BK) {
#pragma unroll
        for (int l = 0; l < ALD; l++) {
            int idx = t + l * 256;
            int row = idx >> 2, seg = idx & 3;
            int gm = m0 + row;
            float4 v = make_float4(0.f, 0.f, 0.f, 0.f);
            if (gm < n) v = *reinterpret_cast<const float4*>(&A[(size_t)gm * IN + k0 + seg * 4]);
            As[seg * 4 + 0][row] = v.x;
            As[seg * 4 + 1][row] = v.y;
            As[seg * 4 + 2][row] = v.z;
            As[seg * 4 + 3][row] = v.w;
        }
#pragma unroll
        for (int l = 0; l < WLD; l++) {
            int idx = t + l * 256;
            reinterpret_cast<float4*>(&Ws[0][0])[idx] =
                reinterpret_cast<const float4*>(&W[(size_t)k0 * OUT])[idx];
        }
        __syncthreads();
#pragma unroll
        for (int kk = 0; kk < BK; kk++) {
            float4 b = *reinterpret_cast<const float4*>(&Ws[kk][ctid * TN]);
            float4 a0 = *reinterpret_cast<const float4*>(&As[kk][rtid * TM]);
            float4 a1 = *reinterpret_cast<const float4*>(&As[kk][rtid * TM + 4]);
            float av[8] = {a0.x, a0.y, a0.z, a0.w, a1.x, a1.y, a1.z, a1.w};
            float bv[4] = {b.x, b.y, b.z, b.w};
#pragma unroll
            for (int i = 0; i < TM; i++)
#pragma unroll
                for (int j = 0; j < TN; j++) acc[i][j] = fmaf(av[i], bv[j], acc[i][j]);
        }
        __syncthreads();
    }

#pragma unroll
    for (int i = 0; i < TM; i++) {
        int gm = m0 + rtid * TM + i;
        if (gm < n) {
            float4 o = make_float4(acc[i][0], acc[i][1], acc[i][2], acc[i][3]);
            *reinterpret_cast<float4*>(&T[(size_t)gm * OUT + ctid * TN]) = o;
        }
    }
}

// ---------------- aggregation: H[d] = relu(sum_{e: dst=d} T[src]*norm + T[d]/deg + bias) ----------------
template <int OUT>
__global__ __launch_bounds__(256) void agg_kernel(const float* __restrict__ T,
                                                  const float* __restrict__ bias,
                                                  float* __restrict__ H, int n) {
    constexpr int VEC = OUT / 32;  // 4 (OUT=128) or 2 (OUT=64)
    int warp = (blockIdx.x * blockDim.x + threadIdx.x) >> 5;
    int lane = threadIdx.x & 31;
    if (warp >= n) return;

    float dn = g_dis[warp];
    float w0 = dn * dn;  // self-loop norm = 1/deg
    float acc[VEC];
    {
        const float* r = &T[(size_t)warp * OUT + lane * VEC];
#pragma unroll
        for (int j = 0; j < VEC; j++) acc[j] = r[j] * w0;
    }
    int p0 = g_off[warp], p1 = g_off[warp + 1];
    for (int p = p0; p < p1; p++) {
        int s = g_csrc[p];
        float w = g_cw[p];
        const float* r = &T[(size_t)s * OUT + lane * VEC];
        if (VEC == 4) {
            float4 v = *reinterpret_cast<const float4*>(r);
            acc[0] = fmaf(v.x, w, acc[0]);
            acc[1] = fmaf(v.y, w, acc[1]);
            acc[2] = fmaf(v.z, w, acc[2]);
            acc[3] = fmaf(v.w, w, acc[3]);
        } else {
            float2 v = *reinterpret_cast<const float2*>(r);
            acc[0] = fmaf(v.x, w, acc[0]);
            acc[1] = fmaf(v.y, w, acc[1]);
        }
    }
    float* o = &H[(size_t)warp * OUT + lane * VEC];
#pragma unroll
    for (int j = 0; j < VEC; j++) {
        float v = acc[j] + bias[lane * VEC + j];
        o[j] = v > 0.f ? v : 0.f;
    }
}

// ---------------- attention head ----------------
__global__ void attn_score_kernel(const float* __restrict__ H,
                                  const float* __restrict__ aW,
                                  const float* __restrict__ ab, int n) {
    int gw = (blockIdx.x * blockDim.x + threadIdx.x) >> 5;
    int lane = threadIdx.x & 31;
    float val = -INFINITY;
    if (gw < n) {
        float v = H[(size_t)gw * 64 + lane] * aW[lane] +
                  H[(size_t)gw * 64 + lane + 32] * aW[lane + 32];
#pragma unroll
        for (int o = 16; o; o >>= 1) v += __shfl_xor_sync(0xFFFFFFFFu, v, o);
        float a = v + ab[0];
        if (lane == 0) g_a[gw] = a;
        val = a;
    }
    __shared__ float sm[8];
    if (lane == 0) sm[threadIdx.x >> 5] = val;
    __syncthreads();
    if (threadIdx.x == 0) {
        float m = sm[0];
#pragma unroll
        for (int i = 1; i < 8; i++) m = fmaxf(m, sm[i]);
        g_red[blockIdx.x] = m;
    }
}

__global__ void reduce_max_kernel(int nb) {
    __shared__ float sm[1024];
    int t = threadIdx.x;
    float m = -INFINITY;
    for (int i = t; i < nb; i += 1024) m = fmaxf(m, g_red[i]);
    sm[t] = m;
    __syncthreads();
    for (int o = 512; o; o >>= 1) {
        if (t < o) sm[t] = fmaxf(sm[t], sm[t + o]);
        __syncthreads();
    }
    if (t == 0) g_scalar[0] = sm[0];
}

__global__ void exp_sum_kernel(int n) {
    __shared__ float sm[256];
    int i = blockIdx.x * blockDim.x + threadIdx.x;
    float e = 0.f;
    if (i < n) {
        e = expf(g_a[i] - g_scalar[0]);
        g_a[i] = e;
    }
    sm[threadIdx.x] = e;
    __syncthreads();
    for (int o = 128; o; o >>= 1) {
        if (threadIdx.x < o) sm[threadIdx.x] += sm[threadIdx.x + o];
        __syncthreads();
    }
    if (threadIdx.x == 0) g_red[blockIdx.x] = sm[0];
}

__global__ void reduce_sum_kernel(int nb) {
    __shared__ float sm[1024];
    int t = threadIdx.x;
    float s = 0.f;
    for (int i = t; i < nb; i += 1024) s += g_red[i];
    sm[t] = s;
    __syncthreads();
    for (int o = 512; o; o >>= 1) {
        if (t < o) sm[t] += sm[t + o];
        __syncthreads();
    }
    if (t == 0) g_scalar[1] = sm[0];
}

__global__ void final_kernel(const float* __restrict__ H,
                             const float* __restrict__ fW,
                             const float* __restrict__ fb,
                             float* __restrict__ out, int n) {
    int gw = (blockIdx.x * blockDim.x + threadIdx.x) >> 5;
    int lane = threadIdx.x & 31;
    if (gw >= n) return;
    float v = H[(size_t)gw * 64 + lane] * fW[lane] +
              H[(size_t)gw * 64 + lane + 32] * fW[lane + 32];
#pragma unroll
    for (int o = 16; o; o >>= 1) v += __shfl_xor_sync(0xFFFFFFFFu, v, o);
    if (lane == 0) {
        float attn = g_a[gw] / g_scalar[1];
        float z = attn * v + fb[0];
        out[gw] = 1.f / (1.f + expf(-z));
        out[n + gw] = attn;
    }
}

// ---------------- launch ----------------
extern "C" void kernel_launch(void* const* d_in, const int* in_sizes, int n_in,
                              void* d_out, int out_size) {
    const float* x   = (const float*)d_in[0];
    const int*   ei  = (const int*)d_in[1];
    const float* W1  = (const float*)d_in[2];
    const float* b1  = (const float*)d_in[3];
    const float* W2  = (const float*)d_in[4];
    const float* b2  = (const float*)d_in[5];
    const float* W3  = (const float*)d_in[6];
    const float* b3  = (const float*)d_in[7];
    const float* aW  = (const float*)d_in[8];
    const float* ab  = (const float*)d_in[9];
    const float* fW  = (const float*)d_in[10];
    const float* fb  = (const float*)d_in[11];
    float* out = (float*)d_out;

    int N = in_sizes[0] / 128;
    int E = in_sizes[1] / 2;
    const int* src = ei;
    const int* dst = ei + E;

    float *t_buf, *h_buf;
    cudaGetSymbolAddress((void**)&t_buf, g_t);
    cudaGetSymbolAddress((void**)&h_buf, g_h);

    // CSR build (reused by all 3 layers)
    zero_kernel<<<(N + 255) / 256, 256>>>(N);
    count_kernel<<<(E + 255) / 256, 256>>>(dst, E);
    scan_kernel<<<1, 1024>>>(N, E);
    fill_kernel<<<(E + 255) / 256, 256>>>(src, dst, E);

    int warpGrid = (N * 32 + 255) / 256;

    // layer 1: x[*,128] @ W1[128,128]
    gemm_kernel<128, 128, 64><<<(N + 63) / 64, 256>>>(x, W1, t_buf, N);
    agg_kernel<128><<<warpGrid, 256>>>(t_buf, b1, h_buf, N);
    // layer 2
    gemm_kernel<128, 128, 64><<<(N + 63) / 64, 256>>>(h_buf, W2, t_buf, N);
    agg_kernel<128><<<warpGrid, 256>>>(t_buf, b2, h_buf, N);
    // layer 3: 128 -> 64
    gemm_kernel<128, 64, 128><<<(N + 127) / 128, 256>>>(h_buf, W3, t_buf, N);
    agg_kernel<64><<<warpGrid, 256>>>(t_buf, b3, h_buf, N);

    // attention softmax over nodes + sigmoid head
    int wblocks = (N * 32 + 255) / 256;  // warp-per-node blocks
    attn_score_kernel<<<wblocks, 256>>>(h_buf, aW, ab, N);
    reduce_max_kernel<<<1, 1024>>>(wblocks);
    exp_sum_kernel<<<(N + 255) / 256, 256>>>(N);
    reduce_sum_kernel<<<1, 1024>>>((N + 255) / 256);
    final_kernel<<<wblocks, 256>>>(h_buf, fW, fb, out, N);
}

// round 3
// speedup vs baseline: 1.0717x; 1.0717x over previous
#include <cuda_runtime.h>
#include <cuda_bf16.h>
#include <math.h>
#include <stdint.h>

// Problem constants (from reference): N=50000, E=800000, dims 128/128/128/64.
#define MAXN 50000
#define MAXE 800000

// ---------------- scratch (device globals; no cudaMalloc allowed) ----------------
__device__ float g_t[MAXN * 128];      // GEMM output (pre-aggregation)
__device__ float g_h[MAXN * 128];      // layer activations
__device__ float g_dis[MAXN];          // rsqrt(deg)
__device__ int   g_deg[MAXN];          // in-degree counts (excl self loop)
__device__ int   g_off[MAXN + 1];      // CSR offsets
__device__ int   g_rank[MAXE];         // per-edge rank within its dst bucket
__device__ int   g_csrc[MAXE];         // CSR src indices (grouped by dst)
__device__ float g_cw[MAXE];           // CSR edge norm weights
__device__ float g_a[MAXN];            // attention logits / exp values
__device__ float g_red[8192];          // block partials
__device__ float g_scalar[2];          // [0]=max, [1]=sum

// ---------------- helpers ----------------
__device__ __forceinline__ void split2(float2 v, uint32_t& hi, uint32_t& lo) {
    __nv_bfloat162 h = __float22bfloat162_rn(v);
    float2 hf = __bfloat1622float2(h);
    __nv_bfloat162 l = __float22bfloat162_rn(make_float2(v.x - hf.x, v.y - hf.y));
    hi = *reinterpret_cast<uint32_t*>(&h);
    lo = *reinterpret_cast<uint32_t*>(&l);
}

__device__ __forceinline__ void mma16816(float* d, uint32_t a0, uint32_t a1,
                                         uint32_t a2, uint32_t a3,
                                         uint32_t b0, uint32_t b1) {
    asm volatile(
        "mma.sync.aligned.m16n8k16.row.col.f32.bf16.bf16.f32 "
        "{%0,%1,%2,%3}, {%4,%5,%6,%7}, {%8,%9}, {%0,%1,%2,%3};"
        : "+f"(d[0]), "+f"(d[1]), "+f"(d[2]), "+f"(d[3])
        : "r"(a0), "r"(a1), "r"(a2), "r"(a3), "r"(b0), "r"(b1));
}

// ---------------- degree / CSR build ----------------
__global__ void zero_kernel(int n) {
    int i = blockIdx.x * blockDim.x + threadIdx.x;
    if (i < n) g_deg[i] = 0;
}

// counts in-degree AND records each edge's arrival rank (used by fill: no 2nd atomic)
__global__ void count_kernel(const int* __restrict__ dst, int e) {
    int i = blockIdx.x * blockDim.x + threadIdx.x;
    if (i < e) g_rank[i] = atomicAdd(&g_deg[dst[i]], 1);
}

// 1 block, 1024 threads: exclusive scan of g_deg -> g_off, and dis = rsqrt(deg+1)
__global__ void scan_kernel(int n, int e) {
    __shared__ int s[1024];
    int t = threadIdx.x;
    int chunk = (n + 1023) >> 10;
    int b = t * chunk;
    int hi = min(b + chunk, n);
    int sum = 0;
    for (int i = b; i < hi; i++) sum += g_deg[i];
    s[t] = sum;
    __syncthreads();
    for (int off = 1; off < 1024; off <<= 1) {
        int v = (t >= off) ? s[t - off] : 0;
        __syncthreads();
        s[t] += v;
        __syncthreads();
    }
    int prefix = s[t] - sum;
    for (int i = b; i < hi; i++) {
        g_off[i] = prefix;
        prefix += g_deg[i];
        g_dis[i] = rsqrtf((float)g_deg[i] + 1.0f);
    }
    if (t == 1023) g_off[n] = e;
}

__global__ void fill_kernel(const int* __restrict__ src, const int* __restrict__ dst, int e) {
    int i = blockIdx.x * blockDim.x + threadIdx.x;
    if (i >= e) return;
    int d = dst[i], s = src[i];
    int p = g_off[d] + g_rank[i];
    g_csrc[p] = s;
    g_cw[p] = g_dis[s] * g_dis[d];
}

// ---------------- mma.sync bf16-split GEMM: T[n,OUT] = A[n,128] @ W[128,OUT] ----------------
// 2-term split: A = Ah + Al, W = Wh + Wl; D = Ah*Wh + Ah*Wl + Al*Wh (fp32 accum).
// CTA: 256 threads (8 warps), tile 128 rows. Warp w owns rows [w*16, w*16+16).
// A fragments loaded straight from global (row-major fp32) and split in-register.
template <int OUT>
__global__ __launch_bounds__(256) void mma_gemm_kernel(const float* __restrict__ A,
                                                       const float* __restrict__ W,
                                                       float* __restrict__ T, int n) {
    constexpr int LDW = 132;               // padded bf16 row stride (k-dim)
    extern __shared__ __nv_bfloat16 sw[];  // Wh[OUT][LDW], Wl[OUT][LDW]
    __nv_bfloat16* Wh = sw;
    __nv_bfloat16* Wl = sw + OUT * LDW;

    int t = threadIdx.x;
    // stage + split + transpose W: global [k][n] fp32 -> smem [n][k] bf16 hi/lo
    for (int i = t; i < 128 * OUT; i += 256) {
        int k = i / OUT, nn = i % OUT;
        float v = W[i];
        __nv_bfloat16 h = __float2bfloat16(v);
        float lo = v - __bfloat162float(h);
        Wh[nn * LDW + k] = h;
        Wl[nn * LDW + k] = __float2bfloat16(lo);
    }
    __syncthreads();

    int warp = t >> 5, lane = t & 31;
    int g = lane >> 2, tg = lane & 3;
    int row0 = blockIdx.x * 128 + warp * 16 + g;
    int row1 = row0 + 8;
    bool v0 = row0 < n, v1 = row1 < n;

    constexpr int NT = OUT / 8;
    float acc[NT][4];
#pragma unroll
    for (int i = 0; i < NT; i++)
#pragma unroll
        for (int j = 0; j < 4; j++) acc[i][j] = 0.f;

    const float* A0 = A + (size_t)row0 * 128;
    const float* A1 = A + (size_t)row1 * 128;

#pragma unroll
    for (int ks = 0; ks < 8; ks++) {
        int k0 = ks * 16 + tg * 2;
        float2 z = make_float2(0.f, 0.f);
        float2 x0 = v0 ? *reinterpret_cast<const float2*>(A0 + k0) : z;
        float2 x1 = v1 ? *reinterpret_cast<const float2*>(A1 + k0) : z;
        float2 x2 = v0 ? *reinterpret_cast<const float2*>(A0 + k0 + 8) : z;
        float2 x3 = v1 ? *reinterpret_cast<const float2*>(A1 + k0 + 8) : z;
        uint32_t ah0, ah1, ah2, ah3, al0, al1, al2, al3;
        split2(x0, ah0, al0);
        split2(x1, ah1, al1);
        split2(x2, ah2, al2);
        split2(x3, ah3, al3);

        const __nv_bfloat16* wh = Wh + g * LDW + ks * 16 + tg * 2;
        const __nv_bfloat16* wl = Wl + g * LDW + ks * 16 + tg * 2;
#pragma unroll
        for (int nt = 0; nt < NT; nt++) {
            uint32_t bh0 = *reinterpret_cast<const uint32_t*>(wh + nt * 8 * LDW);
            uint32_t bh1 = *reinterpret_cast<const uint32_t*>(wh + nt * 8 * LDW + 8);
            uint32_t bl0 = *reinterpret_cast<const uint32_t*>(wl + nt * 8 * LDW);
            uint32_t bl1 = *reinterpret_cast<const uint32_t*>(wl + nt * 8 * LDW + 8);
            mma16816(acc[nt], ah0, ah1, ah2, ah3, bh0, bh1);
            mma16816(acc[nt], ah0, ah1, ah2, ah3, bl0, bl1);
            mma16816(acc[nt], al0, al1, al2, al3, bh0, bh1);
        }
    }

    // epilogue: D frag -> T. c0,c1 = (row0, 2t..2t+1); c2,c3 = (row1, ...)
#pragma unroll
    for (int nt = 0; nt < NT; nt++) {
        int col = nt * 8 + tg * 2;
        if (v0) *reinterpret_cast<float2*>(&T[(size_t)row0 * OUT + col]) =
            make_float2(acc[nt][0], acc[nt][1]);
        if (v1) *reinterpret_cast<float2*>(&T[(size_t)row1 * OUT + col]) =
            make_float2(acc[nt][2], acc[nt][3]);
    }
}

// ---------------- aggregation: H[d] = relu(sum_{e: dst=d} T[src]*norm + T[d]/deg + bias) ----------------
template <int OUT>
__global__ __launch_bounds__(256) void agg_kernel(const float* __restrict__ T,
                                                  const float* __restrict__ bias,
                                                  float* __restrict__ H, int n) {
    constexpr int VEC = OUT / 32;
    int warp = (blockIdx.x * blockDim.x + threadIdx.x) >> 5;
    int lane = threadIdx.x & 31;
    if (warp >= n) return;

    float dn = g_dis[warp];
    float w0 = dn * dn;
    float acc[VEC];
    {
        const float* r = &T[(size_t)warp * OUT + lane * VEC];
#pragma unroll
        for (int j = 0; j < VEC; j++) acc[j] = r[j] * w0;
    }
    int p0 = g_off[warp], p1 = g_off[warp + 1];
    for (int p = p0; p < p1; p++) {
        int s = g_csrc[p];
        float w = g_cw[p];
        const float* r = &T[(size_t)s * OUT + lane * VEC];
        if (VEC == 4) {
            float4 v = *reinterpret_cast<const float4*>(r);
            acc[0] = fmaf(v.x, w, acc[0]);
            acc[1] = fmaf(v.y, w, acc[1]);
            acc[2] = fmaf(v.z, w, acc[2]);
            acc[3] = fmaf(v.w, w, acc[3]);
        } else {
            float2 v = *reinterpret_cast<const float2*>(r);
            acc[0] = fmaf(v.x, w, acc[0]);
            acc[1] = fmaf(v.y, w, acc[1]);
        }
    }
    float* o = &H[(size_t)warp * OUT + lane * VEC];
#pragma unroll
    for (int j = 0; j < VEC; j++) {
        float v = acc[j] + bias[lane * VEC + j];
        o[j] = v > 0.f ? v : 0.f;
    }
}

// ---------------- attention head ----------------
__global__ void attn_score_kernel(const float* __restrict__ H,
                                  const float* __restrict__ aW,
                                  const float* __restrict__ ab, int n) {
    int gw = (blockIdx.x * blockDim.x + threadIdx.x) >> 5;
    int lane = threadIdx.x & 31;
    float val = -INFINITY;
    if (gw < n) {
        float v = H[(size_t)gw * 64 + lane] * aW[lane] +
                  H[(size_t)gw * 64 + lane + 32] * aW[lane + 32];
#pragma unroll
        for (int o = 16; o; o >>= 1) v += __shfl_xor_sync(0xFFFFFFFFu, v, o);
        float a = v + ab[0];
        if (lane == 0) g_a[gw] = a;
        val = a;
    }
    __shared__ float sm[8];
    if (lane == 0) sm[threadIdx.x >> 5] = val;
    __syncthreads();
    if (threadIdx.x == 0) {
        float m = sm[0];
#pragma unroll
        for (int i = 1; i < 8; i++) m = fmaxf(m, sm[i]);
        g_red[blockIdx.x] = m;
    }
}

__global__ void reduce_max_kernel(int nb) {
    __shared__ float sm[1024];
    int t = threadIdx.x;
    float m = -INFINITY;
    for (int i = t; i < nb; i += 1024) m = fmaxf(m, g_red[i]);
    sm[t] = m;
    __syncthreads();
    for (int o = 512; o; o >>= 1) {
        if (t < o) sm[t] = fmaxf(sm[t], sm[t + o]);
        __syncthreads();
    }
    if (t == 0) g_scalar[0] = sm[0];
}

__global__ void exp_sum_kernel(int n) {
    __shared__ float sm[256];
    int i = blockIdx.x * blockDim.x + threadIdx.x;
    float e = 0.f;
    if (i < n) {
        e = expf(g_a[i] - g_scalar[0]);
        g_a[i] = e;
    }
    sm[threadIdx.x] = e;
    __syncthreads();
    for (int o = 128; o; o >>= 1) {
        if (threadIdx.x < o) sm[threadIdx.x] += sm[threadIdx.x + o];
        __syncthreads();
    }
    if (threadIdx.x == 0) g_red[blockIdx.x] = sm[0];
}

__global__ void reduce_sum_kernel(int nb) {
    __shared__ float sm[1024];
    int t = threadIdx.x;
    float s = 0.f;
    for (int i = t; i < nb; i += 1024) s += g_red[i];
    sm[t] = s;
    __syncthreads();
    for (int o = 512; o; o >>= 1) {
        if (t < o) sm[t] += sm[t + o];
        __syncthreads();
    }
    if (t == 0) g_scalar[1] = sm[0];
}

__global__ void final_kernel(const float* __restrict__ H,
                             const float* __restrict__ fW,
                             const float* __restrict__ fb,
                             float* __restrict__ out, int n) {
    int gw = (blockIdx.x * blockDim.x + threadIdx.x) >> 5;
    int lane = threadIdx.x & 31;
    if (gw >= n) return;
    float v = H[(size_t)gw * 64 + lane] * fW[lane] +
              H[(size_t)gw * 64 + lane + 32] * fW[lane + 32];
#pragma unroll
    for (int o = 16; o; o >>= 1) v += __shfl_xor_sync(0xFFFFFFFFu, v, o);
    if (lane == 0) {
        float attn = g_a[gw] / g_scalar[1];
        float z = attn * v + fb[0];
        out[gw] = 1.f / (1.f + expf(-z));
        out[n + gw] = attn;
    }
}

// ---------------- launch ----------------
extern "C" void kernel_launch(void* const* d_in, const int* in_sizes, int n_in,
                              void* d_out, int out_size) {
    const float* x   = (const float*)d_in[0];
    const int*   ei  = (const int*)d_in[1];
    const float* W1  = (const float*)d_in[2];
    const float* b1  = (const float*)d_in[3];
    const float* W2  = (const float*)d_in[4];
    const float* b2  = (const float*)d_in[5];
    const float* W3  = (const float*)d_in[6];
    const float* b3  = (const float*)d_in[7];
    const float* aW  = (const float*)d_in[8];
    const float* ab  = (const float*)d_in[9];
    const float* fW  = (const float*)d_in[10];
    const float* fb  = (const float*)d_in[11];
    float* out = (float*)d_out;

    int N = in_sizes[0] / 128;
    int E = in_sizes[1] / 2;
    const int* src = ei;
    const int* dst = ei + E;

    float *t_buf, *h_buf;
    cudaGetSymbolAddress((void**)&t_buf, g_t);
    cudaGetSymbolAddress((void**)&h_buf, g_h);

    const int SM128 = 2 * 128 * 132 * 2;  // 67584 B
    const int SM64  = 2 * 64 * 132 * 2;   // 33792 B
    cudaFuncSetAttribute(mma_gemm_kernel<128>, cudaFuncAttributeMaxDynamicSharedMemorySize, SM128);
    cudaFuncSetAttribute(mma_gemm_kernel<64>,  cudaFuncAttributeMaxDynamicSharedMemorySize, SM64);

    // CSR build (reused by all 3 layers)
    zero_kernel<<<(N + 255) / 256, 256>>>(N);
    count_kernel<<<(E + 255) / 256, 256>>>(dst, E);
    scan_kernel<<<1, 1024>>>(N, E);
    fill_kernel<<<(E + 255) / 256, 256>>>(src, dst, E);

    int warpGrid = (N * 32 + 255) / 256;
    int mmaGrid = (N + 127) / 128;

    // layer 1: x[*,128] @ W1[128,128]
    mma_gemm_kernel<128><<<mmaGrid, 256, SM128>>>(x, W1, t_buf, N);
    agg_kernel<128><<<warpGrid, 256>>>(t_buf, b1, h_buf, N);
    // layer 2
    mma_gemm_kernel<128><<<mmaGrid, 256, SM128>>>(h_buf, W2, t_buf, N);
    agg_kernel<128><<<warpGrid, 256>>>(t_buf, b2, h_buf, N);
    // layer 3: 128 -> 64
    mma_gemm_kernel<64><<<mmaGrid, 256, SM64>>>(h_buf, W3, t_buf, N);
    agg_kernel<64><<<warpGrid, 256>>>(t_buf, b3, h_buf, N);

    // attention softmax over nodes + sigmoid head
    attn_score_kernel<<<warpGrid, 256>>>(h_buf, aW, ab, N);
    reduce_max_kernel<<<1, 1024>>>(warpGrid);
    exp_sum_kernel<<<(N + 255) / 256, 256>>>(N);
    reduce_sum_kernel<<<1, 1024>>>((N + 255) / 256);
    final_kernel<<<warpGrid, 256>>>(h_buf, fW, fb, out, N);
}

// round 4
// speedup vs baseline: 1.2141x; 1.1328x over previous
#include <cuda_runtime.h>
#include <cuda_bf16.h>
#include <math.h>
#include <stdint.h>

// Problem constants: N=50000, E=800000, dims 128/128/128/64.
#define MAXN 50000
#define MAXE 800000
#define LDW 136   // padded bf16 k-stride for transposed weights

// ---------------- scratch (device globals) ----------------
__device__ float g_t[MAXN * 128];        // GEMM output (pre-aggregation)
__device__ float g_h[MAXN * 128];        // layer activations
__device__ float g_dis[MAXN];            // rsqrt(deg)
__device__ int   g_deg[MAXN];            // in-degree counts
__device__ int   g_off[MAXN + 1];        // CSR offsets
__device__ int   g_rank[MAXE];           // per-edge rank within dst bucket
__device__ int   g_csrc[MAXE];           // CSR src indices (grouped by dst)
__device__ float g_cw[MAXE];             // CSR edge norm weights
__device__ float g_a[MAXN];              // attention logits
__device__ float g_red[16384];           // block partials (max, expsum pairs)
__device__ float g_scalar[2];            // [0]=gmax, [1]=gsum
__device__ __nv_bfloat16 g_w1t[128 * LDW];  // W1^T bf16 padded
__device__ __nv_bfloat16 g_w2t[128 * LDW];
__device__ __nv_bfloat16 g_w3t[64 * LDW];

// ---------------- helpers ----------------
__device__ __forceinline__ void mma16816(float* d, uint32_t a0, uint32_t a1,
                                         uint32_t a2, uint32_t a3,
                                         uint32_t b0, uint32_t b1) {
    asm volatile(
        "mma.sync.aligned.m16n8k16.row.col.f32.bf16.bf16.f32 "
        "{%0,%1,%2,%3}, {%4,%5,%6,%7}, {%8,%9}, {%0,%1,%2,%3};"
        : "+f"(d[0]), "+f"(d[1]), "+f"(d[2]), "+f"(d[3])
        : "r"(a0), "r"(a1), "r"(a2), "r"(a3), "r"(b0), "r"(b1));
}

// ---------------- W prep: fp32 [k][n] -> bf16 transposed padded [n][LDW] ----------------
__global__ void prep_w_kernel(const float* __restrict__ W1, const float* __restrict__ W2,
                              const float* __restrict__ W3) {
    int i = blockIdx.x * blockDim.x + threadIdx.x;
    // W1: 128x128
    if (i < 128 * 128) {
        int k = i >> 7, nn = i & 127;
        g_w1t[nn * LDW + k] = __float2bfloat16(W1[i]);
        g_w2t[nn * LDW + k] = __float2bfloat16(W2[i]);
    }
    // W3: 128x64
    if (i < 128 * 64) {
        int k = i >> 6, nn = i & 63;
        g_w3t[nn * LDW + k] = __float2bfloat16(W3[i]);
    }
}

// ---------------- degree / CSR build ----------------
__global__ void count_kernel(const int* __restrict__ dst, int e) {
    int i = blockIdx.x * blockDim.x + threadIdx.x;
    if (i < e) g_rank[i] = atomicAdd(&g_deg[dst[i]], 1);
}

__global__ void scan_kernel(int n, int e) {
    __shared__ int s[1024];
    int t = threadIdx.x;
    int chunk = (n + 1023) >> 10;
    int b = t * chunk;
    int hi = min(b + chunk, n);
    int sum = 0;
    for (int i = b; i < hi; i++) sum += g_deg[i];
    s[t] = sum;
    __syncthreads();
    for (int off = 1; off < 1024; off <<= 1) {
        int v = (t >= off) ? s[t - off] : 0;
        __syncthreads();
        s[t] += v;
        __syncthreads();
    }
    int prefix = s[t] - sum;
    for (int i = b; i < hi; i++) {
        g_off[i] = prefix;
        prefix += g_deg[i];
        g_dis[i] = rsqrtf((float)g_deg[i] + 1.0f);
    }
    if (t == 1023) g_off[n] = e;
}

__global__ void fill_kernel(const int* __restrict__ src, const int* __restrict__ dst, int e) {
    int i = blockIdx.x * blockDim.x + threadIdx.x;
    if (i >= e) return;
    int d = dst[i], s = src[i];
    int p = g_off[d] + g_rank[i];
    g_csrc[p] = s;
    g_cw[p] = g_dis[s] * g_dis[d];
}

// ---------------- single-pass bf16 mma GEMM: T[n,OUT] = A[n,128] @ W[128,OUT] ----------------
// CTA: 256 threads (8 warps), 128-row tile; warp w owns rows [w*16, w*16+16).
// Wt: pre-split bf16 [OUT][LDW] in global, staged to smem via vector copy.
template <int OUT>
__global__ __launch_bounds__(256) void mma_gemm_kernel(const float* __restrict__ A,
                                                       const __nv_bfloat16* __restrict__ Wt,
                                                       float* __restrict__ T, int n) {
    extern __shared__ __nv_bfloat16 sw[];  // [OUT][LDW]
    int t = threadIdx.x;
    // stage Wt: OUT*LDW bf16 = OUT*17 uint4
    constexpr int NU4 = OUT * LDW / 8;
    for (int i = t; i < NU4; i += 256)
        reinterpret_cast<uint4*>(sw)[i] = reinterpret_cast<const uint4*>(Wt)[i];
    __syncthreads();

    int warp = t >> 5, lane = t & 31;
    int g = lane >> 2, tg = lane & 3;
    int row0 = blockIdx.x * 128 + warp * 16 + g;
    int row1 = row0 + 8;
    bool v0 = row0 < n, v1 = row1 < n;

    constexpr int NT = OUT / 8;
    float acc[NT][4];
#pragma unroll
    for (int i = 0; i < NT; i++)
#pragma unroll
        for (int j = 0; j < 4; j++) acc[i][j] = 0.f;

    const float* A0 = A + (size_t)row0 * 128;
    const float* A1 = A + (size_t)row1 * 128;

#pragma unroll
    for (int ks = 0; ks < 8; ks++) {
        int k0 = ks * 16 + tg * 2;
        float2 z = make_float2(0.f, 0.f);
        float2 x0 = v0 ? *reinterpret_cast<const float2*>(A0 + k0) : z;
        float2 x1 = v1 ? *reinterpret_cast<const float2*>(A1 + k0) : z;
        float2 x2 = v0 ? *reinterpret_cast<const float2*>(A0 + k0 + 8) : z;
        float2 x3 = v1 ? *reinterpret_cast<const float2*>(A1 + k0 + 8) : z;
        __nv_bfloat162 h0 = __float22bfloat162_rn(x0);
        __nv_bfloat162 h1 = __float22bfloat162_rn(x1);
        __nv_bfloat162 h2 = __float22bfloat162_rn(x2);
        __nv_bfloat162 h3 = __float22bfloat162_rn(x3);
        uint32_t a0 = *reinterpret_cast<uint32_t*>(&h0);
        uint32_t a1 = *reinterpret_cast<uint32_t*>(&h1);
        uint32_t a2 = *reinterpret_cast<uint32_t*>(&h2);
        uint32_t a3 = *reinterpret_cast<uint32_t*>(&h3);

        const __nv_bfloat16* wh = sw + g * LDW + ks * 16 + tg * 2;
#pragma unroll
        for (int nt = 0; nt < NT; nt++) {
            uint32_t b0 = *reinterpret_cast<const uint32_t*>(wh + nt * 8 * LDW);
            uint32_t b1 = *reinterpret_cast<const uint32_t*>(wh + nt * 8 * LDW + 8);
            mma16816(acc[nt], a0, a1, a2, a3, b0, b1);
        }
    }

#pragma unroll
    for (int nt = 0; nt < NT; nt++) {
        int col = nt * 8 + tg * 2;
        if (v0) *reinterpret_cast<float2*>(&T[(size_t)row0 * OUT + col]) =
            make_float2(acc[nt][0], acc[nt][1]);
        if (v1) *reinterpret_cast<float2*>(&T[(size_t)row1 * OUT + col]) =
            make_float2(acc[nt][2], acc[nt][3]);
    }
}

// ---------------- aggregation ----------------
template <int OUT>
__global__ __launch_bounds__(256) void agg_kernel(const float* __restrict__ T,
                                                  const float* __restrict__ bias,
                                                  float* __restrict__ H, int n) {
    constexpr int VEC = OUT / 32;
    int warp = (blockIdx.x * blockDim.x + threadIdx.x) >> 5;
    int lane = threadIdx.x & 31;
    if (warp >= n) return;

    float dn = g_dis[warp];
    float w0 = dn * dn;
    float acc[VEC];
    {
        const float* r = &T[(size_t)warp * OUT + lane * VEC];
#pragma unroll
        for (int j = 0; j < VEC; j++) acc[j] = r[j] * w0;
    }
    int p0 = g_off[warp], p1 = g_off[warp + 1];
    for (int p = p0; p < p1; p++) {
        int s = g_csrc[p];
        float w = g_cw[p];
        const float* r = &T[(size_t)s * OUT + lane * VEC];
        if (VEC == 4) {
            float4 v = *reinterpret_cast<const float4*>(r);
            acc[0] = fmaf(v.x, w, acc[0]);
            acc[1] = fmaf(v.y, w, acc[1]);
            acc[2] = fmaf(v.z, w, acc[2]);
            acc[3] = fmaf(v.w, w, acc[3]);
        } else {
            float2 v = *reinterpret_cast<const float2*>(r);
            acc[0] = fmaf(v.x, w, acc[0]);
            acc[1] = fmaf(v.y, w, acc[1]);
        }
    }
    float* o = &H[(size_t)warp * OUT + lane * VEC];
#pragma unroll
    for (int j = 0; j < VEC; j++) {
        float v = acc[j] + bias[lane * VEC + j];
        o[j] = v > 0.f ? v : 0.f;
    }
}

// ---------------- fused attention tail (3 kernels) ----------------
// kernel 1: per-node logit; per-block (max, sum exp(a - bmax)) partials
__global__ void attn_score_kernel(const float* __restrict__ H,
                                  const float* __restrict__ aW,
                                  const float* __restrict__ ab, int n) {
    int gw = (blockIdx.x * blockDim.x + threadIdx.x) >> 5;
    int lane = threadIdx.x & 31;
    float a = -INFINITY;
    if (gw < n) {
        float v = H[(size_t)gw * 64 + lane] * aW[lane] +
                  H[(size_t)gw * 64 + lane + 32] * aW[lane + 32];
#pragma unroll
        for (int o = 16; o; o >>= 1) v += __shfl_xor_sync(0xFFFFFFFFu, v, o);
        a = v + ab[0];
        if (lane == 0) g_a[gw] = a;
    }
    __shared__ float sm[8];
    __shared__ float bmax_s;
    if (lane == 0) sm[threadIdx.x >> 5] = a;
    __syncthreads();
    if (threadIdx.x == 0) {
        float m = sm[0];
#pragma unroll
        for (int i = 1; i < 8; i++) m = fmaxf(m, sm[i]);
        bmax_s = m;
    }
    __syncthreads();
    float bmax = bmax_s;
    float es = (lane == 0 && gw < n) ? expf(a - bmax) : 0.f;
    if (lane == 0) sm[threadIdx.x >> 5] = es;
    __syncthreads();
    if (threadIdx.x == 0) {
        float s = sm[0];
#pragma unroll
        for (int i = 1; i < 8; i++) s += sm[i];
        g_red[blockIdx.x * 2] = bmax;
        g_red[blockIdx.x * 2 + 1] = s;
    }
}

// kernel 2: single block: gmax, gsum = sum bsum_i * exp(bmax_i - gmax)
__global__ void combine_kernel(int nb) {
    __shared__ float sm[1024];
    int t = threadIdx.x;
    float m = -INFINITY;
    for (int i = t; i < nb; i += 1024) m = fmaxf(m, g_red[i * 2]);
    sm[t] = m;
    __syncthreads();
    for (int o = 512; o; o >>= 1) {
        if (t < o) sm[t] = fmaxf(sm[t], sm[t + o]);
        __syncthreads();
    }
    float gmax = sm[0];
    __syncthreads();
    float s = 0.f;
    for (int i = t; i < nb; i += 1024) s += g_red[i * 2 + 1] * expf(g_red[i * 2] - gmax);
    sm[t] = s;
    __syncthreads();
    for (int o = 512; o; o >>= 1) {
        if (t < o) sm[t] += sm[t + o];
        __syncthreads();
    }
    if (t == 0) { g_scalar[0] = gmax; g_scalar[1] = sm[0]; }
}

// kernel 3: attn_i = exp(a_i - gmax)/gsum; out = sigmoid(attn*(h.fcW) + fb)
__global__ void final_kernel(const float* __restrict__ H,
                             const float* __restrict__ fW,
                             const float* __restrict__ fb,
                             float* __restrict__ out, int n) {
    int gw = (blockIdx.x * blockDim.x + threadIdx.x) >> 5;
    int lane = threadIdx.x & 31;
    if (gw >= n) return;
    float v = H[(size_t)gw * 64 + lane] * fW[lane] +
              H[(size_t)gw * 64 + lane + 32] * fW[lane + 32];
#pragma unroll
    for (int o = 16; o; o >>= 1) v += __shfl_xor_sync(0xFFFFFFFFu, v, o);
    if (lane == 0) {
        float attn = expf(g_a[gw] - g_scalar[0]) / g_scalar[1];
        float z = attn * v + fb[0];
        out[gw] = 1.f / (1.f + expf(-z));
        out[n + gw] = attn;
    }
}

// ---------------- launch ----------------
extern "C" void kernel_launch(void* const* d_in, const int* in_sizes, int n_in,
                              void* d_out, int out_size) {
    const float* x   = (const float*)d_in[0];
    const int*   ei  = (const int*)d_in[1];
    const float* W1  = (const float*)d_in[2];
    const float* b1  = (const float*)d_in[3];
    const float* W2  = (const float*)d_in[4];
    const float* b2  = (const float*)d_in[5];
    const float* W3  = (const float*)d_in[6];
    const float* b3  = (const float*)d_in[7];
    const float* aW  = (const float*)d_in[8];
    const float* ab  = (const float*)d_in[9];
    const float* fW  = (const float*)d_in[10];
    const float* fb  = (const float*)d_in[11];
    float* out = (float*)d_out;

    int N = in_sizes[0] / 128;
    int E = in_sizes[1] / 2;
    const int* src = ei;
    const int* dst = ei + E;

    float *t_buf, *h_buf;
    int* deg_ptr;
    __nv_bfloat16 *w1t, *w2t, *w3t;
    cudaGetSymbolAddress((void**)&t_buf, g_t);
    cudaGetSymbolAddress((void**)&h_buf, g_h);
    cudaGetSymbolAddress((void**)&deg_ptr, g_deg);
    cudaGetSymbolAddress((void**)&w1t, g_w1t);
    cudaGetSymbolAddress((void**)&w2t, g_w2t);
    cudaGetSymbolAddress((void**)&w3t, g_w3t);

    const int SM128 = 128 * LDW * 2;  // 34816 B
    const int SM64  = 64 * LDW * 2;   // 17408 B
    cudaFuncSetAttribute(mma_gemm_kernel<128>, cudaFuncAttributeMaxDynamicSharedMemorySize, SM128);
    cudaFuncSetAttribute(mma_gemm_kernel<64>,  cudaFuncAttributeMaxDynamicSharedMemorySize, SM64);

    // weight prep + CSR build
    cudaMemsetAsync(deg_ptr, 0, (size_t)N * sizeof(int));
    prep_w_kernel<<<64, 256>>>(W1, W2, W3);
    count_kernel<<<(E + 255) / 256, 256>>>(dst, E);
    scan_kernel<<<1, 1024>>>(N, E);
    fill_kernel<<<(E + 255) / 256, 256>>>(src, dst, E);

    int warpGrid = (N * 32 + 255) / 256;
    int mmaGrid = (N + 127) / 128;

    mma_gemm_kernel<128><<<mmaGrid, 256, SM128>>>(x, w1t, t_buf, N);
    agg_kernel<128><<<warpGrid, 256>>>(t_buf, b1, h_buf, N);
    mma_gemm_kernel<128><<<mmaGrid, 256, SM128>>>(h_buf, w2t, t_buf, N);
    agg_kernel<128><<<warpGrid, 256>>>(t_buf, b2, h_buf, N);
    mma_gemm_kernel<64><<<mmaGrid, 256, SM64>>>(h_buf, w3t, t_buf, N);
    agg_kernel<64><<<warpGrid, 256>>>(t_buf, b3, h_buf, N);

    attn_score_kernel<<<warpGrid, 256>>>(h_buf, aW, ab, N);
    combine_kernel<<<1, 1024>>>(warpGrid);
    final_kernel<<<warpGrid, 256>>>(h_buf, fW, fb, out, N);
}

// round 5
// speedup vs baseline: 1.2667x; 1.0433x over previous
#include <cuda_runtime.h>
#include <cuda_bf16.h>
#include <math.h>
#include <stdint.h>

// Problem constants: N=50000, E=800000, dims 128/128/128/64.
#define MAXN 50000
#define MAXE 800000
#define LDW 136   // padded bf16 k-stride for transposed weights

// ---------------- scratch (device globals) ----------------
__device__ __nv_bfloat16 g_tb[MAXN * 128];  // GEMM output (bf16, pre-aggregation)
__device__ __nv_bfloat16 g_hb[MAXN * 128];  // layer activations (bf16)
__device__ float g_h[MAXN * 64];            // layer-3 activations (fp32, feeds tail)
__device__ float g_dis[MAXN];               // rsqrt(deg)
__device__ int   g_deg[MAXN];               // in-degree counts
__device__ int   g_off[MAXN + 1];           // CSR offsets
__device__ int   g_rank[MAXE];              // per-edge rank within dst bucket
__device__ int2  g_edge[MAXE];              // packed CSR: (src, weight-bits)
__device__ float g_a[MAXN];                 // attention logits
__device__ float g_red[16384];              // block partials
__device__ float g_scalar[2];               // [0]=gmax, [1]=gsum
__device__ __nv_bfloat16 g_w1t[128 * LDW];
__device__ __nv_bfloat16 g_w2t[128 * LDW];
__device__ __nv_bfloat16 g_w3t[64 * LDW];

// ---------------- helpers ----------------
__device__ __forceinline__ void mma16816(float* d, uint32_t a0, uint32_t a1,
                                         uint32_t a2, uint32_t a3,
                                         uint32_t b0, uint32_t b1) {
    asm volatile(
        "mma.sync.aligned.m16n8k16.row.col.f32.bf16.bf16.f32 "
        "{%0,%1,%2,%3}, {%4,%5,%6,%7}, {%8,%9}, {%0,%1,%2,%3};"
        : "+f"(d[0]), "+f"(d[1]), "+f"(d[2]), "+f"(d[3])
        : "r"(a0), "r"(a1), "r"(a2), "r"(a3), "r"(b0), "r"(b1));
}

// ---------------- W prep ----------------
__global__ void prep_w_kernel(const float* __restrict__ W1, const float* __restrict__ W2,
                              const float* __restrict__ W3) {
    int i = blockIdx.x * blockDim.x + threadIdx.x;
    if (i < 128 * 128) {
        int k = i >> 7, nn = i & 127;
        g_w1t[nn * LDW + k] = __float2bfloat16(W1[i]);
        g_w2t[nn * LDW + k] = __float2bfloat16(W2[i]);
    }
    if (i < 128 * 64) {
        int k = i >> 6, nn = i & 63;
        g_w3t[nn * LDW + k] = __float2bfloat16(W3[i]);
    }
}

// ---------------- degree / CSR build ----------------
__global__ void count_kernel(const int* __restrict__ dst, int e) {
    int i = blockIdx.x * blockDim.x + threadIdx.x;
    if (i < e) g_rank[i] = atomicAdd(&g_deg[dst[i]], 1);
}

__global__ void scan_kernel(int n, int e) {
    __shared__ int s[1024];
    int t = threadIdx.x;
    int chunk = (n + 1023) >> 10;
    int b = t * chunk;
    int hi = min(b + chunk, n);
    int sum = 0;
    for (int i = b; i < hi; i++) sum += g_deg[i];
    s[t] = sum;
    __syncthreads();
    for (int off = 1; off < 1024; off <<= 1) {
        int v = (t >= off) ? s[t - off] : 0;
        __syncthreads();
        s[t] += v;
        __syncthreads();
    }
    int prefix = s[t] - sum;
    for (int i = b; i < hi; i++) {
        g_off[i] = prefix;
        prefix += g_deg[i];
        g_dis[i] = rsqrtf((float)g_deg[i] + 1.0f);
    }
    if (t == 1023) g_off[n] = e;
}

__global__ void fill_kernel(const int* __restrict__ src, const int* __restrict__ dst, int e) {
    int i = blockIdx.x * blockDim.x + threadIdx.x;
    if (i >= e) return;
    int d = dst[i], s = src[i];
    int p = g_off[d] + g_rank[i];
    float w = g_dis[s] * g_dis[d];
    g_edge[p] = make_int2(s, __float_as_int(w));
}

// ---------------- bf16 mma GEMM: T[n,OUT](bf16) = A[n,128] @ W[128,OUT] ----------------
// AF = float (layer 1) or __nv_bfloat16 (layers 2,3).
template <int OUT, typename AF>
__global__ __launch_bounds__(256) void mma_gemm_kernel(const AF* __restrict__ A,
                                                       const __nv_bfloat16* __restrict__ Wt,
                                                       __nv_bfloat16* __restrict__ T, int n) {
    extern __shared__ __nv_bfloat16 sw[];  // [OUT][LDW]
    int t = threadIdx.x;
    constexpr int NU4 = OUT * LDW / 8;
    for (int i = t; i < NU4; i += 256)
        reinterpret_cast<uint4*>(sw)[i] = reinterpret_cast<const uint4*>(Wt)[i];
    __syncthreads();

    int warp = t >> 5, lane = t & 31;
    int g = lane >> 2, tg = lane & 3;
    int row0 = blockIdx.x * 128 + warp * 16 + g;
    int row1 = row0 + 8;
    bool v0 = row0 < n, v1 = row1 < n;

    constexpr int NT = OUT / 8;
    float acc[NT][4];
#pragma unroll
    for (int i = 0; i < NT; i++)
#pragma unroll
        for (int j = 0; j < 4; j++) acc[i][j] = 0.f;

    const AF* A0 = A + (size_t)row0 * 128;
    const AF* A1 = A + (size_t)row1 * 128;

#pragma unroll
    for (int ks = 0; ks < 8; ks++) {
        int k0 = ks * 16 + tg * 2;
        uint32_t a0, a1, a2, a3;
        if (sizeof(AF) == 4) {  // fp32 A: load float2 and convert
            const float* F0 = (const float*)A0;
            const float* F1 = (const float*)A1;
            float2 z = make_float2(0.f, 0.f);
            float2 x0 = v0 ? *reinterpret_cast<const float2*>(F0 + k0) : z;
            float2 x1 = v1 ? *reinterpret_cast<const float2*>(F1 + k0) : z;
            float2 x2 = v0 ? *reinterpret_cast<const float2*>(F0 + k0 + 8) : z;
            float2 x3 = v1 ? *reinterpret_cast<const float2*>(F1 + k0 + 8) : z;
            __nv_bfloat162 h0 = __float22bfloat162_rn(x0);
            __nv_bfloat162 h1 = __float22bfloat162_rn(x1);
            __nv_bfloat162 h2 = __float22bfloat162_rn(x2);
            __nv_bfloat162 h3 = __float22bfloat162_rn(x3);
            a0 = *reinterpret_cast<uint32_t*>(&h0);
            a1 = *reinterpret_cast<uint32_t*>(&h1);
            a2 = *reinterpret_cast<uint32_t*>(&h2);
            a3 = *reinterpret_cast<uint32_t*>(&h3);
        } else {  // bf16 A: direct fragment loads
            const __nv_bfloat16* B0 = (const __nv_bfloat16*)A0;
            const __nv_bfloat16* B1 = (const __nv_bfloat16*)A1;
            a0 = v0 ? *reinterpret_cast<const uint32_t*>(B0 + k0) : 0u;
            a1 = v1 ? *reinterpret_cast<const uint32_t*>(B1 + k0) : 0u;
            a2 = v0 ? *reinterpret_cast<const uint32_t*>(B0 + k0 + 8) : 0u;
            a3 = v1 ? *reinterpret_cast<const uint32_t*>(B1 + k0 + 8) : 0u;
        }

        const __nv_bfloat16* wh = sw + g * LDW + ks * 16 + tg * 2;
#pragma unroll
        for (int nt = 0; nt < NT; nt++) {
            uint32_t b0 = *reinterpret_cast<const uint32_t*>(wh + nt * 8 * LDW);
            uint32_t b1 = *reinterpret_cast<const uint32_t*>(wh + nt * 8 * LDW + 8);
            mma16816(acc[nt], a0, a1, a2, a3, b0, b1);
        }
    }

#pragma unroll
    for (int nt = 0; nt < NT; nt++) {
        int col = nt * 8 + tg * 2;
        if (v0) {
            __nv_bfloat162 o = __float22bfloat162_rn(make_float2(acc[nt][0], acc[nt][1]));
            *reinterpret_cast<__nv_bfloat162*>(&T[(size_t)row0 * OUT + col]) = o;
        }
        if (v1) {
            __nv_bfloat162 o = __float22bfloat162_rn(make_float2(acc[nt][2], acc[nt][3]));
            *reinterpret_cast<__nv_bfloat162*>(&T[(size_t)row1 * OUT + col]) = o;
        }
    }
}

// ---------------- aggregation (bf16 gather) ----------------
// warp per node; lane-batched edge records broadcast via shfl.
// OUTBF16: write bf16 H (layers 1,2); else fp32 H (layer 3).
template <int OUT, bool OUTBF16>
__global__ __launch_bounds__(256) void agg_kernel(const __nv_bfloat16* __restrict__ T,
                                                  const float* __restrict__ bias,
                                                  void* __restrict__ Hout, int n) {
    constexpr int VEC = OUT / 32;  // 4 or 2 bf16 per lane
    int warp = (blockIdx.x * blockDim.x + threadIdx.x) >> 5;
    int lane = threadIdx.x & 31;
    if (warp >= n) return;

    float dn = g_dis[warp];
    float w0 = dn * dn;
    float acc[VEC];
    {
        const __nv_bfloat16* r = &T[(size_t)warp * OUT + lane * VEC];
        if (VEC == 4) {
            uint2 u = *reinterpret_cast<const uint2*>(r);
            float2 f0 = __bfloat1622float2(*reinterpret_cast<__nv_bfloat162*>(&u.x));
            float2 f1 = __bfloat1622float2(*reinterpret_cast<__nv_bfloat162*>(&u.y));
            acc[0] = f0.x * w0; acc[1] = f0.y * w0;
            acc[2] = f1.x * w0; acc[3] = f1.y * w0;
        } else {
            uint32_t u = *reinterpret_cast<const uint32_t*>(r);
            float2 f0 = __bfloat1622float2(*reinterpret_cast<__nv_bfloat162*>(&u));
            acc[0] = f0.x * w0; acc[1] = f0.y * w0;
        }
    }

    int p0 = g_off[warp];
    int cnt = g_off[warp + 1] - p0;
    int2 ed = (lane < cnt) ? g_edge[p0 + lane] : make_int2(0, 0);
    for (int j = 0; j < cnt; j++) {
        int jb = j & 31;
        if (j && jb == 0)
            ed = (j + lane < cnt) ? g_edge[p0 + j + lane] : make_int2(0, 0);
        int s = __shfl_sync(0xFFFFFFFFu, ed.x, jb);
        float w = __int_as_float(__shfl_sync(0xFFFFFFFFu, ed.y, jb));
        const __nv_bfloat16* r = &T[(size_t)s * OUT + lane * VEC];
        if (VEC == 4) {
            uint2 u = *reinterpret_cast<const uint2*>(r);
            float2 f0 = __bfloat1622float2(*reinterpret_cast<__nv_bfloat162*>(&u.x));
            float2 f1 = __bfloat1622float2(*reinterpret_cast<__nv_bfloat162*>(&u.y));
            acc[0] = fmaf(f0.x, w, acc[0]);
            acc[1] = fmaf(f0.y, w, acc[1]);
            acc[2] = fmaf(f1.x, w, acc[2]);
            acc[3] = fmaf(f1.y, w, acc[3]);
        } else {
            uint32_t u = *reinterpret_cast<const uint32_t*>(r);
            float2 f0 = __bfloat1622float2(*reinterpret_cast<__nv_bfloat162*>(&u));
            acc[0] = fmaf(f0.x, w, acc[0]);
            acc[1] = fmaf(f0.y, w, acc[1]);
        }
    }

#pragma unroll
    for (int j = 0; j < VEC; j++) {
        float v = acc[j] + bias[lane * VEC + j];
        acc[j] = v > 0.f ? v : 0.f;
    }
    if (OUTBF16) {
        __nv_bfloat16* o = (__nv_bfloat16*)Hout + (size_t)warp * OUT + lane * VEC;
        if (VEC == 4) {
            __nv_bfloat162 o0 = __float22bfloat162_rn(make_float2(acc[0], acc[1]));
            __nv_bfloat162 o1 = __float22bfloat162_rn(make_float2(acc[2], acc[3]));
            uint2 u;
            u.x = *reinterpret_cast<uint32_t*>(&o0);
            u.y = *reinterpret_cast<uint32_t*>(&o1);
            *reinterpret_cast<uint2*>(o) = u;
        } else {
            __nv_bfloat162 o0 = __float22bfloat162_rn(make_float2(acc[0], acc[1]));
            *reinterpret_cast<__nv_bfloat162*>(o) = o0;
        }
    } else {
        float* o = (float*)Hout + (size_t)warp * OUT + lane * VEC;
#pragma unroll
        for (int j = 0; j < VEC; j++) o[j] = acc[j];
    }
}

// ---------------- fused attention tail ----------------
__global__ void attn_score_kernel(const float* __restrict__ H,
                                  const float* __restrict__ aW,
                                  const float* __restrict__ ab, int n) {
    int gw = (blockIdx.x * blockDim.x + threadIdx.x) >> 5;
    int lane = threadIdx.x & 31;
    float a = -INFINITY;
    if (gw < n) {
        float v = H[(size_t)gw * 64 + lane] * aW[lane] +
                  H[(size_t)gw * 64 + lane + 32] * aW[lane + 32];
#pragma unroll
        for (int o = 16; o; o >>= 1) v += __shfl_xor_sync(0xFFFFFFFFu, v, o);
        a = v + ab[0];
        if (lane == 0) g_a[gw] = a;
    }
    __shared__ float sm[8];
    __shared__ float bmax_s;
    if (lane == 0) sm[threadIdx.x >> 5] = a;
    __syncthreads();
    if (threadIdx.x == 0) {
        float m = sm[0];
#pragma unroll
        for (int i = 1; i < 8; i++) m = fmaxf(m, sm[i]);
        bmax_s = m;
    }
    __syncthreads();
    float bmax = bmax_s;
    float es = (lane == 0 && gw < n) ? expf(a - bmax) : 0.f;
    if (lane == 0) sm[threadIdx.x >> 5] = es;
    __syncthreads();
    if (threadIdx.x == 0) {
        float s = sm[0];
#pragma unroll
        for (int i = 1; i < 8; i++) s += sm[i];
        g_red[blockIdx.x * 2] = bmax;
        g_red[blockIdx.x * 2 + 1] = s;
    }
}

__global__ void combine_kernel(int nb) {
    __shared__ float sm[1024];
    int t = threadIdx.x;
    float m = -INFINITY;
    for (int i = t; i < nb; i += 1024) m = fmaxf(m, g_red[i * 2]);
    sm[t] = m;
    __syncthreads();
    for (int o = 512; o; o >>= 1) {
        if (t < o) sm[t] = fmaxf(sm[t], sm[t + o]);
        __syncthreads();
    }
    float gmax = sm[0];
    __syncthreads();
    float s = 0.f;
    for (int i = t; i < nb; i += 1024) s += g_red[i * 2 + 1] * expf(g_red[i * 2] - gmax);
    sm[t] = s;
    __syncthreads();
    for (int o = 512; o; o >>= 1) {
        if (t < o) sm[t] += sm[t + o];
        __syncthreads();
    }
    if (t == 0) { g_scalar[0] = gmax; g_scalar[1] = sm[0]; }
}

__global__ void final_kernel(const float* __restrict__ H,
                             const float* __restrict__ fW,
                             const float* __restrict__ fb,
                             float* __restrict__ out, int n) {
    int gw = (blockIdx.x * blockDim.x + threadIdx.x) >> 5;
    int lane = threadIdx.x & 31;
    if (gw >= n) return;
    float v = H[(size_t)gw * 64 + lane] * fW[lane] +
              H[(size_t)gw * 64 + lane + 32] * fW[lane + 32];
#pragma unroll
    for (int o = 16; o; o >>= 1) v += __shfl_xor_sync(0xFFFFFFFFu, v, o);
    if (lane == 0) {
        float attn = expf(g_a[gw] - g_scalar[0]) / g_scalar[1];
        float z = attn * v + fb[0];
        out[gw] = 1.f / (1.f + expf(-z));
        out[n + gw] = attn;
    }
}

// ---------------- launch ----------------
extern "C" void kernel_launch(void* const* d_in, const int* in_sizes, int n_in,
                              void* d_out, int out_size) {
    const float* x   = (const float*)d_in[0];
    const int*   ei  = (const int*)d_in[1];
    const float* W1  = (const float*)d_in[2];
    const float* b1  = (const float*)d_in[3];
    const float* W2  = (const float*)d_in[4];
    const float* b2  = (const float*)d_in[5];
    const float* W3  = (const float*)d_in[6];
    const float* b3  = (const float*)d_in[7];
    const float* aW  = (const float*)d_in[8];
    const float* ab  = (const float*)d_in[9];
    const float* fW  = (const float*)d_in[10];
    const float* fb  = (const float*)d_in[11];
    float* out = (float*)d_out;

    int N = in_sizes[0] / 128;
    int E = in_sizes[1] / 2;
    const int* src = ei;
    const int* dst = ei + E;

    __nv_bfloat16 *tb, *hb, *w1t, *w2t, *w3t;
    float* h3;
    int* deg_ptr;
    cudaGetSymbolAddress((void**)&tb, g_tb);
    cudaGetSymbolAddress((void**)&hb, g_hb);
    cudaGetSymbolAddress((void**)&h3, g_h);
    cudaGetSymbolAddress((void**)&deg_ptr, g_deg);
    cudaGetSymbolAddress((void**)&w1t, g_w1t);
    cudaGetSymbolAddress((void**)&w2t, g_w2t);
    cudaGetSymbolAddress((void**)&w3t, g_w3t);

    const int SM128 = 128 * LDW * 2;
    const int SM64  = 64 * LDW * 2;
    cudaFuncSetAttribute((const void*)mma_gemm_kernel<128, float>,
                         cudaFuncAttributeMaxDynamicSharedMemorySize, SM128);
    cudaFuncSetAttribute((const void*)mma_gemm_kernel<128, __nv_bfloat16>,
                         cudaFuncAttributeMaxDynamicSharedMemorySize, SM128);
    cudaFuncSetAttribute((const void*)mma_gemm_kernel<64, __nv_bfloat16>,
                         cudaFuncAttributeMaxDynamicSharedMemorySize, SM64);

    cudaMemsetAsync(deg_ptr, 0, (size_t)N * sizeof(int));
    prep_w_kernel<<<64, 256>>>(W1, W2, W3);
    count_kernel<<<(E + 255) / 256, 256>>>(dst, E);
    scan_kernel<<<1, 1024>>>(N, E);
    fill_kernel<<<(E + 255) / 256, 256>>>(src, dst, E);

    int warpGrid = (N * 32 + 255) / 256;
    int mmaGrid = (N + 127) / 128;

    mma_gemm_kernel<128, float><<<mmaGrid, 256, SM128>>>(x, w1t, tb, N);
    agg_kernel<128, true><<<warpGrid, 256>>>(tb, b1, hb, N);
    mma_gemm_kernel<128, __nv_bfloat16><<<mmaGrid, 256, SM128>>>(hb, w2t, tb, N);
    agg_kernel<128, true><<<warpGrid, 256>>>(tb, b2, hb, N);
    mma_gemm_kernel<64, __nv_bfloat16><<<mmaGrid, 256, SM64>>>(hb, w3t, tb, N);
    agg_kernel<64, false><<<warpGrid, 256>>>(tb, b3, h3, N);

    attn_score_kernel<<<warpGrid, 256>>>(h3, aW, ab, N);
    combine_kernel<<<1, 1024>>>(warpGrid);
    final_kernel<<<warpGrid, 256>>>(h3, fW, fb, out, N);
}

// round 6
// speedup vs baseline: 1.7902x; 1.4133x over previous
#include <cuda_runtime.h>
#include <cuda_bf16.h>
#include <math.h>
#include <stdint.h>

// Problem constants: N=50000, E=800000, dims 128/128/128/64.
#define MAXN 50000
#define MAXE 800000
#define LDW 136     // padded bf16 k-stride for transposed weights
#define SCAN_B 2048 // elements per scan block

// ---------------- scratch (device globals) ----------------
__device__ __nv_bfloat16 g_tb[MAXN * 128];  // GEMM output (bf16)
__device__ __nv_bfloat16 g_hb[MAXN * 128];  // layer activations (bf16)
__device__ float g_h[MAXN * 64];            // layer-3 activations (fp32)
__device__ float g_dis[MAXN];               // rsqrt(deg)
__device__ int   g_deg[MAXN];               // in-degree counts
__device__ int   g_off[MAXN + 1];           // CSR offsets
__device__ int   g_rank[MAXE];              // per-edge rank within dst bucket
__device__ int   g_csrc[MAXE];              // CSR src indices (grouped by dst)
__device__ float g_a[MAXN];                 // attention logits
__device__ float g_red[16384];              // block partials
__device__ float g_scalar[2];               // [0]=gmax, [1]=gsum
__device__ int   g_bsum[64];                // scan block sums
__device__ int   g_boff[64];                // scan block offsets
__device__ __nv_bfloat16 g_w1t[128 * LDW];
__device__ __nv_bfloat16 g_w2t[128 * LDW];
__device__ __nv_bfloat16 g_w3t[64 * LDW];

// ---------------- helpers ----------------
__device__ __forceinline__ void mma16816(float* d, uint32_t a0, uint32_t a1,
                                         uint32_t a2, uint32_t a3,
                                         uint32_t b0, uint32_t b1) {
    asm volatile(
        "mma.sync.aligned.m16n8k16.row.col.f32.bf16.bf16.f32 "
        "{%0,%1,%2,%3}, {%4,%5,%6,%7}, {%8,%9}, {%0,%1,%2,%3};"
        : "+f"(d[0]), "+f"(d[1]), "+f"(d[2]), "+f"(d[3])
        : "r"(a0), "r"(a1), "r"(a2), "r"(a3), "r"(b0), "r"(b1));
}

__device__ __forceinline__ float2 bf2f(uint32_t u) {
    return __bfloat1622float2(*reinterpret_cast<__nv_bfloat162*>(&u));
}

// ---------------- W prep ----------------
__global__ void prep_w_kernel(const float* __restrict__ W1, const float* __restrict__ W2,
                              const float* __restrict__ W3) {
    int i = blockIdx.x * blockDim.x + threadIdx.x;
    if (i < 128 * 128) {
        int k = i >> 7, nn = i & 127;
        g_w1t[nn * LDW + k] = __float2bfloat16(W1[i]);
        g_w2t[nn * LDW + k] = __float2bfloat16(W2[i]);
    }
    if (i < 128 * 64) {
        int k = i >> 6, nn = i & 63;
        g_w3t[nn * LDW + k] = __float2bfloat16(W3[i]);
    }
}

// ---------------- degree / CSR build ----------------
__global__ void count_kernel(const int* __restrict__ dst, int e) {
    int i = blockIdx.x * blockDim.x + threadIdx.x;
    if (i < e) g_rank[i] = atomicAdd(&g_deg[dst[i]], 1);
}

// phase 1: per-block sums of deg
__global__ void scan1_kernel(int n) {
    __shared__ int sm[256];
    int base = blockIdx.x * SCAN_B + threadIdx.x * 8;
    int s = 0;
#pragma unroll
    for (int i = 0; i < 8; i++) {
        int idx = base + i;
        if (idx < n) s += g_deg[idx];
    }
    sm[threadIdx.x] = s;
    __syncthreads();
    for (int o = 128; o; o >>= 1) {
        if (threadIdx.x < o) sm[threadIdx.x] += sm[threadIdx.x + o];
        __syncthreads();
    }
    if (threadIdx.x == 0) g_bsum[blockIdx.x] = sm[0];
}

// phase 2: tiny exclusive scan of block sums
__global__ void scan2_kernel(int nb, int n, int e) {
    if (threadIdx.x == 0) {
        int acc = 0;
        for (int i = 0; i < nb; i++) { g_boff[i] = acc; acc += g_bsum[i]; }
        g_off[n] = e;
    }
}

// phase 3: block-local exclusive scan, write offsets + dis
__global__ void scan3_kernel(int n) {
    __shared__ int sm[256];
    int t = threadIdx.x;
    int base = blockIdx.x * SCAN_B + t * 8;
    int loc[8];
    int s = 0;
#pragma unroll
    for (int i = 0; i < 8; i++) {
        int idx = base + i;
        loc[i] = (idx < n) ? g_deg[idx] : 0;
        s += loc[i];
    }
    sm[t] = s;
    __syncthreads();
    for (int off = 1; off < 256; off <<= 1) {
        int v = (t >= off) ? sm[t - off] : 0;
        __syncthreads();
        sm[t] += v;
        __syncthreads();
    }
    int prefix = g_boff[blockIdx.x] + sm[t] - s;
#pragma unroll
    for (int i = 0; i < 8; i++) {
        int idx = base + i;
        if (idx < n) {
            g_off[idx] = prefix;
            prefix += loc[i];
            g_dis[idx] = rsqrtf((float)loc[i] + 1.0f);
        }
    }
}

__global__ void fill_kernel(const int* __restrict__ src, const int* __restrict__ dst, int e) {
    int i = blockIdx.x * blockDim.x + threadIdx.x;
    if (i >= e) return;
    g_csrc[g_off[dst[i]] + g_rank[i]] = src[i];
}

// ---------------- bf16 mma GEMM: T[n,OUT](bf16) = A[n,128] @ W[128,OUT] ----------------
template <int OUT, typename AF>
__global__ __launch_bounds__(256) void mma_gemm_kernel(const AF* __restrict__ A,
                                                       const __nv_bfloat16* __restrict__ Wt,
                                                       __nv_bfloat16* __restrict__ T, int n) {
    extern __shared__ __nv_bfloat16 sw[];  // [OUT][LDW]
    int t = threadIdx.x;
    constexpr int NU4 = OUT * LDW / 8;
    for (int i = t; i < NU4; i += 256)
        reinterpret_cast<uint4*>(sw)[i] = reinterpret_cast<const uint4*>(Wt)[i];
    __syncthreads();

    int warp = t >> 5, lane = t & 31;
    int g = lane >> 2, tg = lane & 3;
    int row0 = blockIdx.x * 128 + warp * 16 + g;
    int row1 = row0 + 8;
    bool v0 = row0 < n, v1 = row1 < n;

    constexpr int NT = OUT / 8;
    float acc[NT][4];
#pragma unroll
    for (int i = 0; i < NT; i++)
#pragma unroll
        for (int j = 0; j < 4; j++) acc[i][j] = 0.f;

    const AF* A0 = A + (size_t)row0 * 128;
    const AF* A1 = A + (size_t)row1 * 128;

#pragma unroll
    for (int ks = 0; ks < 8; ks++) {
        int k0 = ks * 16 + tg * 2;
        uint32_t a0, a1, a2, a3;
        if (sizeof(AF) == 4) {
            const float* F0 = (const float*)A0;
            const float* F1 = (const float*)A1;
            float2 z = make_float2(0.f, 0.f);
            float2 x0 = v0 ? *reinterpret_cast<const float2*>(F0 + k0) : z;
            float2 x1 = v1 ? *reinterpret_cast<const float2*>(F1 + k0) : z;
            float2 x2 = v0 ? *reinterpret_cast<const float2*>(F0 + k0 + 8) : z;
            float2 x3 = v1 ? *reinterpret_cast<const float2*>(F1 + k0 + 8) : z;
            __nv_bfloat162 h0 = __float22bfloat162_rn(x0);
            __nv_bfloat162 h1 = __float22bfloat162_rn(x1);
            __nv_bfloat162 h2 = __float22bfloat162_rn(x2);
            __nv_bfloat162 h3 = __float22bfloat162_rn(x3);
            a0 = *reinterpret_cast<uint32_t*>(&h0);
            a1 = *reinterpret_cast<uint32_t*>(&h1);
            a2 = *reinterpret_cast<uint32_t*>(&h2);
            a3 = *reinterpret_cast<uint32_t*>(&h3);
        } else {
            const __nv_bfloat16* B0 = (const __nv_bfloat16*)A0;
            const __nv_bfloat16* B1 = (const __nv_bfloat16*)A1;
            a0 = v0 ? *reinterpret_cast<const uint32_t*>(B0 + k0) : 0u;
            a1 = v1 ? *reinterpret_cast<const uint32_t*>(B1 + k0) : 0u;
            a2 = v0 ? *reinterpret_cast<const uint32_t*>(B0 + k0 + 8) : 0u;
            a3 = v1 ? *reinterpret_cast<const uint32_t*>(B1 + k0 + 8) : 0u;
        }

        const __nv_bfloat16* wh = sw + g * LDW + ks * 16 + tg * 2;
#pragma unroll
        for (int nt = 0; nt < NT; nt++) {
            uint32_t b0 = *reinterpret_cast<const uint32_t*>(wh + nt * 8 * LDW);
            uint32_t b1 = *reinterpret_cast<const uint32_t*>(wh + nt * 8 * LDW + 8);
            mma16816(acc[nt], a0, a1, a2, a3, b0, b1);
        }
    }

#pragma unroll
    for (int nt = 0; nt < NT; nt++) {
        int col = nt * 8 + tg * 2;
        if (v0) {
            __nv_bfloat162 o = __float22bfloat162_rn(make_float2(acc[nt][0], acc[nt][1]));
            *reinterpret_cast<__nv_bfloat162*>(&T[(size_t)row0 * OUT + col]) = o;
        }
        if (v1) {
            __nv_bfloat162 o = __float22bfloat162_rn(make_float2(acc[nt][2], acc[nt][3]));
            *reinterpret_cast<__nv_bfloat162*>(&T[(size_t)row1 * OUT + col]) = o;
        }
    }
}

// ---------------- aggregation layers 1,2 (bf16->bf16, OUT=128, unroll x4) ----------------
__global__ __launch_bounds__(256) void agg128_kernel(const __nv_bfloat16* __restrict__ T,
                                                     const float* __restrict__ bias,
                                                     __nv_bfloat16* __restrict__ H, int n) {
    int warp = (blockIdx.x * blockDim.x + threadIdx.x) >> 5;
    int lane = threadIdx.x & 31;
    if (warp >= n) return;

    float dn = g_dis[warp];
    float w0 = dn * dn;
    float acc[4];
    {
        uint2 u = *reinterpret_cast<const uint2*>(&T[(size_t)warp * 128 + lane * 4]);
        float2 f0 = bf2f(u.x), f1 = bf2f(u.y);
        acc[0] = f0.x * w0; acc[1] = f0.y * w0;
        acc[2] = f1.x * w0; acc[3] = f1.y * w0;
    }

    int p0 = g_off[warp];
    int cnt = g_off[warp + 1] - p0;
    int sv = (lane < cnt) ? g_csrc[p0 + lane] : 0;
    int j = 0;
    for (; j + 4 <= cnt; j += 4) {
        if ((j & 31) == 0 && j)
            sv = (j + lane < cnt) ? g_csrc[p0 + j + lane] : 0;
        int jb = j & 31;
        int s0 = __shfl_sync(0xFFFFFFFFu, sv, jb);
        int s1 = __shfl_sync(0xFFFFFFFFu, sv, jb + 1);
        int s2 = __shfl_sync(0xFFFFFFFFu, sv, jb + 2);
        int s3 = __shfl_sync(0xFFFFFFFFu, sv, jb + 3);
        float ww0 = g_dis[s0] * dn, ww1 = g_dis[s1] * dn;
        float ww2 = g_dis[s2] * dn, ww3 = g_dis[s3] * dn;
        uint2 u0 = *reinterpret_cast<const uint2*>(&T[(size_t)s0 * 128 + lane * 4]);
        uint2 u1 = *reinterpret_cast<const uint2*>(&T[(size_t)s1 * 128 + lane * 4]);
        uint2 u2 = *reinterpret_cast<const uint2*>(&T[(size_t)s2 * 128 + lane * 4]);
        uint2 u3 = *reinterpret_cast<const uint2*>(&T[(size_t)s3 * 128 + lane * 4]);
        float2 a0 = bf2f(u0.x), b0 = bf2f(u0.y);
        float2 a1 = bf2f(u1.x), b1 = bf2f(u1.y);
        float2 a2 = bf2f(u2.x), b2 = bf2f(u2.y);
        float2 a3 = bf2f(u3.x), b3 = bf2f(u3.y);
        acc[0] = fmaf(a0.x, ww0, acc[0]); acc[1] = fmaf(a0.y, ww0, acc[1]);
        acc[2] = fmaf(b0.x, ww0, acc[2]); acc[3] = fmaf(b0.y, ww0, acc[3]);
        acc[0] = fmaf(a1.x, ww1, acc[0]); acc[1] = fmaf(a1.y, ww1, acc[1]);
        acc[2] = fmaf(b1.x, ww1, acc[2]); acc[3] = fmaf(b1.y, ww1, acc[3]);
        acc[0] = fmaf(a2.x, ww2, acc[0]); acc[1] = fmaf(a2.y, ww2, acc[1]);
        acc[2] = fmaf(b2.x, ww2, acc[2]); acc[3] = fmaf(b2.y, ww2, acc[3]);
        acc[0] = fmaf(a3.x, ww3, acc[0]); acc[1] = fmaf(a3.y, ww3, acc[1]);
        acc[2] = fmaf(b3.x, ww3, acc[2]); acc[3] = fmaf(b3.y, ww3, acc[3]);
    }
    for (; j < cnt; j++) {
        if ((j & 31) == 0 && j)
            sv = (j + lane < cnt) ? g_csrc[p0 + j + lane] : 0;
        int s = __shfl_sync(0xFFFFFFFFu, sv, j & 31);
        float w = g_dis[s] * dn;
        uint2 u = *reinterpret_cast<const uint2*>(&T[(size_t)s * 128 + lane * 4]);
        float2 f0 = bf2f(u.x), f1 = bf2f(u.y);
        acc[0] = fmaf(f0.x, w, acc[0]); acc[1] = fmaf(f0.y, w, acc[1]);
        acc[2] = fmaf(f1.x, w, acc[2]); acc[3] = fmaf(f1.y, w, acc[3]);
    }

#pragma unroll
    for (int q = 0; q < 4; q++) {
        float v = acc[q] + bias[lane * 4 + q];
        acc[q] = v > 0.f ? v : 0.f;
    }
    __nv_bfloat162 o0 = __float22bfloat162_rn(make_float2(acc[0], acc[1]));
    __nv_bfloat162 o1 = __float22bfloat162_rn(make_float2(acc[2], acc[3]));
    uint2 u;
    u.x = *reinterpret_cast<uint32_t*>(&o0);
    u.y = *reinterpret_cast<uint32_t*>(&o1);
    *reinterpret_cast<uint2*>(&g_hb[(size_t)warp * 128 + lane * 4]) = u;
    (void)H;
}

// ---------------- fused layer-3 agg + attention score (OUT=64) ----------------
__global__ __launch_bounds__(256) void agg3_attn_kernel(const __nv_bfloat16* __restrict__ T,
                                                        const float* __restrict__ bias,
                                                        const float* __restrict__ aW,
                                                        const float* __restrict__ ab,
                                                        float* __restrict__ H, int n) {
    int warp = (blockIdx.x * blockDim.x + threadIdx.x) >> 5;
    int lane = threadIdx.x & 31;
    float a = -INFINITY;

    if (warp < n) {
        float dn = g_dis[warp];
        float w0 = dn * dn;
        float acc0, acc1;
        {
            uint32_t u = *reinterpret_cast<const uint32_t*>(&T[(size_t)warp * 64 + lane * 2]);
            float2 f = bf2f(u);
            acc0 = f.x * w0; acc1 = f.y * w0;
        }
        int p0 = g_off[warp];
        int cnt = g_off[warp + 1] - p0;
        int sv = (lane < cnt) ? g_csrc[p0 + lane] : 0;
        int j = 0;
        for (; j + 4 <= cnt; j += 4) {
            if ((j & 31) == 0 && j)
                sv = (j + lane < cnt) ? g_csrc[p0 + j + lane] : 0;
            int jb = j & 31;
            int s0 = __shfl_sync(0xFFFFFFFFu, sv, jb);
            int s1 = __shfl_sync(0xFFFFFFFFu, sv, jb + 1);
            int s2 = __shfl_sync(0xFFFFFFFFu, sv, jb + 2);
            int s3 = __shfl_sync(0xFFFFFFFFu, sv, jb + 3);
            float ww0 = g_dis[s0] * dn, ww1 = g_dis[s1] * dn;
            float ww2 = g_dis[s2] * dn, ww3 = g_dis[s3] * dn;
            uint32_t u0 = *reinterpret_cast<const uint32_t*>(&T[(size_t)s0 * 64 + lane * 2]);
            uint32_t u1 = *reinterpret_cast<const uint32_t*>(&T[(size_t)s1 * 64 + lane * 2]);
            uint32_t u2 = *reinterpret_cast<const uint32_t*>(&T[(size_t)s2 * 64 + lane * 2]);
            uint32_t u3 = *reinterpret_cast<const uint32_t*>(&T[(size_t)s3 * 64 + lane * 2]);
            float2 f0 = bf2f(u0), f1 = bf2f(u1), f2 = bf2f(u2), f3 = bf2f(u3);
            acc0 = fmaf(f0.x, ww0, acc0); acc1 = fmaf(f0.y, ww0, acc1);
            acc0 = fmaf(f1.x, ww1, acc0); acc1 = fmaf(f1.y, ww1, acc1);
            acc0 = fmaf(f2.x, ww2, acc0); acc1 = fmaf(f2.y, ww2, acc1);
            acc0 = fmaf(f3.x, ww3, acc0); acc1 = fmaf(f3.y, ww3, acc1);
        }
        for (; j < cnt; j++) {
            if ((j & 31) == 0 && j)
                sv = (j + lane < cnt) ? g_csrc[p0 + j + lane] : 0;
            int s = __shfl_sync(0xFFFFFFFFu, sv, j & 31);
            float w = g_dis[s] * dn;
            uint32_t u = *reinterpret_cast<const uint32_t*>(&T[(size_t)s * 64 + lane * 2]);
            float2 f = bf2f(u);
            acc0 = fmaf(f.x, w, acc0); acc1 = fmaf(f.y, w, acc1);
        }

        float v0 = acc0 + bias[lane * 2];
        float v1 = acc1 + bias[lane * 2 + 1];
        v0 = v0 > 0.f ? v0 : 0.f;
        v1 = v1 > 0.f ? v1 : 0.f;
        *reinterpret_cast<float2*>(&H[(size_t)warp * 64 + lane * 2]) = make_float2(v0, v1);

        // attention logit: dot(h, aW)
        float part = v0 * aW[lane * 2] + v1 * aW[lane * 2 + 1];
#pragma unroll
        for (int o = 16; o; o >>= 1) part += __shfl_xor_sync(0xFFFFFFFFu, part, o);
        a = part + ab[0];
        if (lane == 0) g_a[warp] = a;
    }

    // block partials: max and sum of exp(a - bmax)
    __shared__ float sm[8];
    __shared__ float bmax_s;
    if (lane == 0) sm[threadIdx.x >> 5] = a;
    __syncthreads();
    if (threadIdx.x == 0) {
        float m = sm[0];
#pragma unroll
        for (int i = 1; i < 8; i++) m = fmaxf(m, sm[i]);
        bmax_s = m;
    }
    __syncthreads();
    float bmax = bmax_s;
    float es = (lane == 0 && warp < n) ? expf(a - bmax) : 0.f;
    if (lane == 0) sm[threadIdx.x >> 5] = es;
    __syncthreads();
    if (threadIdx.x == 0) {
        float s = sm[0];
#pragma unroll
        for (int i = 1; i < 8; i++) s += sm[i];
        g_red[blockIdx.x * 2] = bmax;
        g_red[blockIdx.x * 2 + 1] = s;
    }
}

// ---------------- softmax combine + final ----------------
__global__ void combine_kernel(int nb) {
    __shared__ float sm[1024];
    int t = threadIdx.x;
    float m = -INFINITY;
    for (int i = t; i < nb; i += 1024) m = fmaxf(m, g_red[i * 2]);
    sm[t] = m;
    __syncthreads();
    for (int o = 512; o; o >>= 1) {
        if (t < o) sm[t] = fmaxf(sm[t], sm[t + o]);
        __syncthreads();
    }
    float gmax = sm[0];
    __syncthreads();
    float s = 0.f;
    for (int i = t; i < nb; i += 1024) s += g_red[i * 2 + 1] * expf(g_red[i * 2] - gmax);
    sm[t] = s;
    __syncthreads();
    for (int o = 512; o; o >>= 1) {
        if (t < o) sm[t] += sm[t + o];
        __syncthreads();
    }
    if (t == 0) { g_scalar[0] = gmax; g_scalar[1] = sm[0]; }
}

__global__ void final_kernel(const float* __restrict__ H,
                             const float* __restrict__ fW,
                             const float* __restrict__ fb,
                             float* __restrict__ out, int n) {
    int gw = (blockIdx.x * blockDim.x + threadIdx.x) >> 5;
    int lane = threadIdx.x & 31;
    if (gw >= n) return;
    float v = H[(size_t)gw * 64 + lane] * fW[lane] +
              H[(size_t)gw * 64 + lane + 32] * fW[lane + 32];
#pragma unroll
    for (int o = 16; o; o >>= 1) v += __shfl_xor_sync(0xFFFFFFFFu, v, o);
    if (lane == 0) {
        float attn = expf(g_a[gw] - g_scalar[0]) / g_scalar[1];
        float z = attn * v + fb[0];
        out[gw] = 1.f / (1.f + expf(-z));
        out[n + gw] = attn;
    }
}

// ---------------- launch ----------------
extern "C" void kernel_launch(void* const* d_in, const int* in_sizes, int n_in,
                              void* d_out, int out_size) {
    const float* x   = (const float*)d_in[0];
    const int*   ei  = (const int*)d_in[1];
    const float* W1  = (const float*)d_in[2];
    const float* b1  = (const float*)d_in[3];
    const float* W2  = (const float*)d_in[4];
    const float* b2  = (const float*)d_in[5];
    const float* W3  = (const float*)d_in[6];
    const float* b3  = (const float*)d_in[7];
    const float* aW  = (const float*)d_in[8];
    const float* ab  = (const float*)d_in[9];
    const float* fW  = (const float*)d_in[10];
    const float* fb  = (const float*)d_in[11];
    float* out = (float*)d_out;

    int N = in_sizes[0] / 128;
    int E = in_sizes[1] / 2;
    const int* src = ei;
    const int* dst = ei + E;

    __nv_bfloat16 *tb, *hb, *w1t, *w2t, *w3t;
    float* h3;
    int* deg_ptr;
    cudaGetSymbolAddress((void**)&tb, g_tb);
    cudaGetSymbolAddress((void**)&hb, g_hb);
    cudaGetSymbolAddress((void**)&h3, g_h);
    cudaGetSymbolAddress((void**)&deg_ptr, g_deg);
    cudaGetSymbolAddress((void**)&w1t, g_w1t);
    cudaGetSymbolAddress((void**)&w2t, g_w2t);
    cudaGetSymbolAddress((void**)&w3t, g_w3t);

    const int SM128 = 128 * LDW * 2;
    const int SM64  = 64 * LDW * 2;
    cudaFuncSetAttribute((const void*)mma_gemm_kernel<128, float>,
                         cudaFuncAttributeMaxDynamicSharedMemorySize, SM128);
    cudaFuncSetAttribute((const void*)mma_gemm_kernel<128, __nv_bfloat16>,
                         cudaFuncAttributeMaxDynamicSharedMemorySize, SM128);
    cudaFuncSetAttribute((const void*)mma_gemm_kernel<64, __nv_bfloat16>,
                         cudaFuncAttributeMaxDynamicSharedMemorySize, SM64);

    cudaMemsetAsync(deg_ptr, 0, (size_t)N * sizeof(int));
    prep_w_kernel<<<64, 256>>>(W1, W2, W3);
    count_kernel<<<(E + 255) / 256, 256>>>(dst, E);
    int nb = (N + SCAN_B - 1) / SCAN_B;
    scan1_kernel<<<nb, 256>>>(N);
    scan2_kernel<<<1, 32>>>(nb, N, E);
    scan3_kernel<<<nb, 256>>>(N);
    fill_kernel<<<(E + 255) / 256, 256>>>(src, dst, E);

    int warpGrid = (N * 32 + 255) / 256;
    int mmaGrid = (N + 127) / 128;

    mma_gemm_kernel<128, float><<<mmaGrid, 256, SM128>>>(x, w1t, tb, N);
    agg128_kernel<<<warpGrid, 256>>>(tb, b1, hb, N);
    mma_gemm_kernel<128, __nv_bfloat16><<<mmaGrid, 256, SM128>>>(hb, w2t, tb, N);
    agg128_kernel<<<warpGrid, 256>>>(tb, b2, hb, N);
    mma_gemm_kernel<64, __nv_bfloat16><<<mmaGrid, 256, SM64>>>(hb, w3t, tb, N);
    agg3_attn_kernel<<<warpGrid, 256>>>(tb, b3, aW, ab, h3, N);

    combine_kernel<<<1, 1024>>>(warpGrid);
    final_kernel<<<warpGrid, 256>>>(h3, fW, fb, out, N);
}

// round 7
// speedup vs baseline: 1.8371x; 1.0262x over previous
#include <cuda_runtime.h>
#include <cuda_bf16.h>
#include <math.h>
#include <stdint.h>

// Problem constants: N=50000, E=800000, dims 128/128/128/64.
#define MAXN 50000
#define MAXE 800000
#define LDW 136     // padded bf16 k-stride for transposed weights
#define SCAN_B 2048 // elements per scan block
#define PREP_B 64   // blocks reserved for weight prep inside count kernel

// ---------------- scratch (device globals) ----------------
__device__ __nv_bfloat16 g_tb[MAXN * 128];  // GEMM output (bf16)
__device__ __nv_bfloat16 g_hb[MAXN * 128];  // layer activations (bf16)
__device__ float g_h[MAXN * 64];            // layer-3 activations (fp32)
__device__ float g_dis[MAXN];               // rsqrt(deg)
__device__ int   g_deg[MAXN];               // in-degree counts
__device__ int   g_off[MAXN + 1];           // CSR offsets
__device__ int   g_rank[MAXE];              // per-edge rank within dst bucket
__device__ int   g_csrc[MAXE];              // CSR src indices (grouped by dst)
__device__ float g_a[MAXN];                 // attention logits
__device__ float g_red[16384];              // block partials
__device__ float g_scalar[2];               // [0]=gmax, [1]=gsum
__device__ int   g_bsum[64];                // scan block sums
__device__ __nv_bfloat16 g_w1t[128 * LDW];
__device__ __nv_bfloat16 g_w2t[128 * LDW];
__device__ __nv_bfloat16 g_w3t[64 * LDW];

// ---------------- helpers ----------------
__device__ __forceinline__ void mma16816(float* d, uint32_t a0, uint32_t a1,
                                         uint32_t a2, uint32_t a3,
                                         uint32_t b0, uint32_t b1) {
    asm volatile(
        "mma.sync.aligned.m16n8k16.row.col.f32.bf16.bf16.f32 "
        "{%0,%1,%2,%3}, {%4,%5,%6,%7}, {%8,%9}, {%0,%1,%2,%3};"
        : "+f"(d[0]), "+f"(d[1]), "+f"(d[2]), "+f"(d[3])
        : "r"(a0), "r"(a1), "r"(a2), "r"(a3), "r"(b0), "r"(b1));
}

__device__ __forceinline__ float2 bf2f(uint32_t u) {
    return __bfloat1622float2(*reinterpret_cast<__nv_bfloat162*>(&u));
}

// ---------------- fused weight-prep + degree count ----------------
// blocks [0, PREP_B): transpose/convert weights; blocks [PREP_B, ...): count degrees.
__global__ void prep_count_kernel(const float* __restrict__ W1, const float* __restrict__ W2,
                                  const float* __restrict__ W3,
                                  const int* __restrict__ dst, int e) {
    if (blockIdx.x < PREP_B) {
        int i = blockIdx.x * 256 + threadIdx.x;
        if (i < 128 * 128) {
            int k = i >> 7, nn = i & 127;
            g_w1t[nn * LDW + k] = __float2bfloat16(W1[i]);
            g_w2t[nn * LDW + k] = __float2bfloat16(W2[i]);
        }
        if (i < 128 * 64) {
            int k = i >> 6, nn = i & 63;
            g_w3t[nn * LDW + k] = __float2bfloat16(W3[i]);
        }
    } else {
        int i = (blockIdx.x - PREP_B) * 256 + threadIdx.x;
        if (i < e) g_rank[i] = atomicAdd(&g_deg[dst[i]], 1);
    }
}

// ---------------- scan phase 1: per-block sums ----------------
__global__ void scan1_kernel(int n, int e) {
    __shared__ int sm[256];
    int base = blockIdx.x * SCAN_B + threadIdx.x * 8;
    int s = 0;
#pragma unroll
    for (int i = 0; i < 8; i++) {
        int idx = base + i;
        if (idx < n) s += g_deg[idx];
    }
    sm[threadIdx.x] = s;
    __syncthreads();
    for (int o = 128; o; o >>= 1) {
        if (threadIdx.x < o) sm[threadIdx.x] += sm[threadIdx.x + o];
        __syncthreads();
    }
    if (threadIdx.x == 0) {
        g_bsum[blockIdx.x] = sm[0];
        if (blockIdx.x == 0) g_off[n] = e;
    }
}

// ---------------- scan phase 2: block-local scan + inline block prefix ----------------
__global__ void scan3_kernel(int n) {
    __shared__ int sm[256];
    __shared__ int boff_s;
    int t = threadIdx.x;
    // lane-parallel prefix over earlier block sums (nb <= 64)
    if (t < 32) {
        int v = 0;
        for (int i = t; i < (int)blockIdx.x; i += 32) v += g_bsum[i];
#pragma unroll
        for (int o = 16; o; o >>= 1) v += __shfl_xor_sync(0xFFFFFFFFu, v, o);
        if (t == 0) boff_s = v;
    }
    int base = blockIdx.x * SCAN_B + t * 8;
    int loc[8];
    int s = 0;
#pragma unroll
    for (int i = 0; i < 8; i++) {
        int idx = base + i;
        loc[i] = (idx < n) ? g_deg[idx] : 0;
        s += loc[i];
    }
    sm[t] = s;
    __syncthreads();
    for (int off = 1; off < 256; off <<= 1) {
        int v = (t >= off) ? sm[t - off] : 0;
        __syncthreads();
        sm[t] += v;
        __syncthreads();
    }
    int prefix = boff_s + sm[t] - s;
#pragma unroll
    for (int i = 0; i < 8; i++) {
        int idx = base + i;
        if (idx < n) {
            g_off[idx] = prefix;
            prefix += loc[i];
            g_dis[idx] = rsqrtf((float)loc[i] + 1.0f);
        }
    }
}

__global__ void fill_kernel(const int* __restrict__ src, const int* __restrict__ dst, int e) {
    int i = blockIdx.x * blockDim.x + threadIdx.x;
    if (i >= e) return;
    g_csrc[g_off[dst[i]] + g_rank[i]] = src[i];
}

// ---------------- bf16 mma GEMM: T[n,OUT](bf16) = A[n,128] @ W[128,OUT] ----------------
template <int OUT, typename AF>
__global__ __launch_bounds__(256) void mma_gemm_kernel(const AF* __restrict__ A,
                                                       const __nv_bfloat16* __restrict__ Wt,
                                                       __nv_bfloat16* __restrict__ T, int n) {
    extern __shared__ __nv_bfloat16 sw[];  // [OUT][LDW]
    int t = threadIdx.x;
    constexpr int NU4 = OUT * LDW / 8;
    for (int i = t; i < NU4; i += 256)
        reinterpret_cast<uint4*>(sw)[i] = reinterpret_cast<const uint4*>(Wt)[i];
    __syncthreads();

    int warp = t >> 5, lane = t & 31;
    int g = lane >> 2, tg = lane & 3;
    int row0 = blockIdx.x * 128 + warp * 16 + g;
    int row1 = row0 + 8;
    bool v0 = row0 < n, v1 = row1 < n;

    constexpr int NT = OUT / 8;
    float acc[NT][4];
#pragma unroll
    for (int i = 0; i < NT; i++)
#pragma unroll
        for (int j = 0; j < 4; j++) acc[i][j] = 0.f;

    const AF* A0 = A + (size_t)row0 * 128;
    const AF* A1 = A + (size_t)row1 * 128;

#pragma unroll
    for (int ks = 0; ks < 8; ks++) {
        int k0 = ks * 16 + tg * 2;
        uint32_t a0, a1, a2, a3;
        if (sizeof(AF) == 4) {
            const float* F0 = (const float*)A0;
            const float* F1 = (const float*)A1;
            float2 z = make_float2(0.f, 0.f);
            float2 x0 = v0 ? *reinterpret_cast<const float2*>(F0 + k0) : z;
            float2 x1 = v1 ? *reinterpret_cast<const float2*>(F1 + k0) : z;
            float2 x2 = v0 ? *reinterpret_cast<const float2*>(F0 + k0 + 8) : z;
            float2 x3 = v1 ? *reinterpret_cast<const float2*>(F1 + k0 + 8) : z;
            __nv_bfloat162 h0 = __float22bfloat162_rn(x0);
            __nv_bfloat162 h1 = __float22bfloat162_rn(x1);
            __nv_bfloat162 h2 = __float22bfloat162_rn(x2);
            __nv_bfloat162 h3 = __float22bfloat162_rn(x3);
            a0 = *reinterpret_cast<uint32_t*>(&h0);
            a1 = *reinterpret_cast<uint32_t*>(&h1);
            a2 = *reinterpret_cast<uint32_t*>(&h2);
            a3 = *reinterpret_cast<uint32_t*>(&h3);
        } else {
            const __nv_bfloat16* B0 = (const __nv_bfloat16*)A0;
            const __nv_bfloat16* B1 = (const __nv_bfloat16*)A1;
            a0 = v0 ? *reinterpret_cast<const uint32_t*>(B0 + k0) : 0u;
            a1 = v1 ? *reinterpret_cast<const uint32_t*>(B1 + k0) : 0u;
            a2 = v0 ? *reinterpret_cast<const uint32_t*>(B0 + k0 + 8) : 0u;
            a3 = v1 ? *reinterpret_cast<const uint32_t*>(B1 + k0 + 8) : 0u;
        }

        const __nv_bfloat16* wh = sw + g * LDW + ks * 16 + tg * 2;
#pragma unroll
        for (int nt = 0; nt < NT; nt++) {
            uint32_t b0 = *reinterpret_cast<const uint32_t*>(wh + nt * 8 * LDW);
            uint32_t b1 = *reinterpret_cast<const uint32_t*>(wh + nt * 8 * LDW + 8);
            mma16816(acc[nt], a0, a1, a2, a3, b0, b1);
        }
    }

#pragma unroll
    for (int nt = 0; nt < NT; nt++) {
        int col = nt * 8 + tg * 2;
        if (v0) {
            __nv_bfloat162 o = __float22bfloat162_rn(make_float2(acc[nt][0], acc[nt][1]));
            *reinterpret_cast<__nv_bfloat162*>(&T[(size_t)row0 * OUT + col]) = o;
        }
        if (v1) {
            __nv_bfloat162 o = __float22bfloat162_rn(make_float2(acc[nt][2], acc[nt][3]));
            *reinterpret_cast<__nv_bfloat162*>(&T[(size_t)row1 * OUT + col]) = o;
        }
    }
}

// ---------------- aggregation layers 1,2 (bf16->bf16, OUT=128, unroll x8) ----------------
__global__ __launch_bounds__(256) void agg128_kernel(const __nv_bfloat16* __restrict__ T,
                                                     const float* __restrict__ bias,
                                                     __nv_bfloat16* __restrict__ H, int n) {
    int warp = (blockIdx.x * blockDim.x + threadIdx.x) >> 5;
    int lane = threadIdx.x & 31;
    if (warp >= n) return;

    float dn = g_dis[warp];
    float w0 = dn * dn;
    float acc[4];
    {
        uint2 u = *reinterpret_cast<const uint2*>(&T[(size_t)warp * 128 + lane * 4]);
        float2 f0 = bf2f(u.x), f1 = bf2f(u.y);
        acc[0] = f0.x * w0; acc[1] = f0.y * w0;
        acc[2] = f1.x * w0; acc[3] = f1.y * w0;
    }

    int p0 = g_off[warp];
    int cnt = g_off[warp + 1] - p0;
    int sv = (lane < cnt) ? g_csrc[p0 + lane] : 0;
    int j = 0;
    for (; j + 8 <= cnt; j += 8) {
        if ((j & 31) == 0 && j)
            sv = (j + lane < cnt) ? g_csrc[p0 + j + lane] : 0;
        int jb = j & 31;
        int s[8];
#pragma unroll
        for (int q = 0; q < 8; q++) s[q] = __shfl_sync(0xFFFFFFFFu, sv, jb + q);
        float w[8];
#pragma unroll
        for (int q = 0; q < 8; q++) w[q] = g_dis[s[q]] * dn;
        uint2 u[8];
#pragma unroll
        for (int q = 0; q < 8; q++)
            u[q] = *reinterpret_cast<const uint2*>(&T[(size_t)s[q] * 128 + lane * 4]);
#pragma unroll
        for (int q = 0; q < 8; q++) {
            float2 f0 = bf2f(u[q].x), f1 = bf2f(u[q].y);
            acc[0] = fmaf(f0.x, w[q], acc[0]); acc[1] = fmaf(f0.y, w[q], acc[1]);
            acc[2] = fmaf(f1.x, w[q], acc[2]); acc[3] = fmaf(f1.y, w[q], acc[3]);
        }
    }
    for (; j < cnt; j++) {
        if ((j & 31) == 0 && j)
            sv = (j + lane < cnt) ? g_csrc[p0 + j + lane] : 0;
        int s = __shfl_sync(0xFFFFFFFFu, sv, j & 31);
        float w = g_dis[s] * dn;
        uint2 u = *reinterpret_cast<const uint2*>(&T[(size_t)s * 128 + lane * 4]);
        float2 f0 = bf2f(u.x), f1 = bf2f(u.y);
        acc[0] = fmaf(f0.x, w, acc[0]); acc[1] = fmaf(f0.y, w, acc[1]);
        acc[2] = fmaf(f1.x, w, acc[2]); acc[3] = fmaf(f1.y, w, acc[3]);
    }

#pragma unroll
    for (int q = 0; q < 4; q++) {
        float v = acc[q] + bias[lane * 4 + q];
        acc[q] = v > 0.f ? v : 0.f;
    }
    __nv_bfloat162 o0 = __float22bfloat162_rn(make_float2(acc[0], acc[1]));
    __nv_bfloat162 o1 = __float22bfloat162_rn(make_float2(acc[2], acc[3]));
    uint2 u;
    u.x = *reinterpret_cast<uint32_t*>(&o0);
    u.y = *reinterpret_cast<uint32_t*>(&o1);
    *reinterpret_cast<uint2*>(&H[(size_t)warp * 128 + lane * 4]) = u;
}

// ---------------- fused layer-3 agg + attention score (OUT=64, unroll x8) ----------------
__global__ __launch_bounds__(256) void agg3_attn_kernel(const __nv_bfloat16* __restrict__ T,
                                                        const float* __restrict__ bias,
                                                        const float* __restrict__ aW,
                                                        const float* __restrict__ ab,
                                                        float* __restrict__ H, int n) {
    int warp = (blockIdx.x * blockDim.x + threadIdx.x) >> 5;
    int lane = threadIdx.x & 31;
    float a = -INFINITY;

    if (warp < n) {
        float dn = g_dis[warp];
        float w0 = dn * dn;
        float acc0, acc1;
        {
            uint32_t u = *reinterpret_cast<const uint32_t*>(&T[(size_t)warp * 64 + lane * 2]);
            float2 f = bf2f(u);
            acc0 = f.x * w0; acc1 = f.y * w0;
        }
        int p0 = g_off[warp];
        int cnt = g_off[warp + 1] - p0;
        int sv = (lane < cnt) ? g_csrc[p0 + lane] : 0;
        int j = 0;
        for (; j + 8 <= cnt; j += 8) {
            if ((j & 31) == 0 && j)
                sv = (j + lane < cnt) ? g_csrc[p0 + j + lane] : 0;
            int jb = j & 31;
            int s[8];
#pragma unroll
            for (int q = 0; q < 8; q++) s[q] = __shfl_sync(0xFFFFFFFFu, sv, jb + q);
            float w[8];
#pragma unroll
            for (int q = 0; q < 8; q++) w[q] = g_dis[s[q]] * dn;
            uint32_t u[8];
#pragma unroll
            for (int q = 0; q < 8; q++)
                u[q] = *reinterpret_cast<const uint32_t*>(&T[(size_t)s[q] * 64 + lane * 2]);
#pragma unroll
            for (int q = 0; q < 8; q++) {
                float2 f = bf2f(u[q]);
                acc0 = fmaf(f.x, w[q], acc0); acc1 = fmaf(f.y, w[q], acc1);
            }
        }
        for (; j < cnt; j++) {
            if ((j & 31) == 0 && j)
                sv = (j + lane < cnt) ? g_csrc[p0 + j + lane] : 0;
            int s = __shfl_sync(0xFFFFFFFFu, sv, j & 31);
            float w = g_dis[s] * dn;
            uint32_t u = *reinterpret_cast<const uint32_t*>(&T[(size_t)s * 64 + lane * 2]);
            float2 f = bf2f(u);
            acc0 = fmaf(f.x, w, acc0); acc1 = fmaf(f.y, w, acc1);
        }

        float v0 = acc0 + bias[lane * 2];
        float v1 = acc1 + bias[lane * 2 + 1];
        v0 = v0 > 0.f ? v0 : 0.f;
        v1 = v1 > 0.f ? v1 : 0.f;
        *reinterpret_cast<float2*>(&H[(size_t)warp * 64 + lane * 2]) = make_float2(v0, v1);

        float part = v0 * aW[lane * 2] + v1 * aW[lane * 2 + 1];
#pragma unroll
        for (int o = 16; o; o >>= 1) part += __shfl_xor_sync(0xFFFFFFFFu, part, o);
        a = part + ab[0];
        if (lane == 0) g_a[warp] = a;
    }

    __shared__ float sm[8];
    __shared__ float bmax_s;
    if (lane == 0) sm[threadIdx.x >> 5] = a;
    __syncthreads();
    if (threadIdx.x == 0) {
        float m = sm[0];
#pragma unroll
        for (int i = 1; i < 8; i++) m = fmaxf(m, sm[i]);
        bmax_s = m;
    }
    __syncthreads();
    float bmax = bmax_s;
    float es = (lane == 0 && warp < n) ? expf(a - bmax) : 0.f;
    if (lane == 0) sm[threadIdx.x >> 5] = es;
    __syncthreads();
    if (threadIdx.x == 0) {
        float s = sm[0];
#pragma unroll
        for (int i = 1; i < 8; i++) s += sm[i];
        g_red[blockIdx.x * 2] = bmax;
        g_red[blockIdx.x * 2 + 1] = s;
    }
}

// ---------------- softmax combine + final ----------------
__global__ void combine_kernel(int nb) {
    __shared__ float sm[1024];
    int t = threadIdx.x;
    float m = -INFINITY;
    for (int i = t; i < nb; i += 1024) m = fmaxf(m, g_red[i * 2]);
    sm[t] = m;
    __syncthreads();
    for (int o = 512; o; o >>= 1) {
        if (t < o) sm[t] = fmaxf(sm[t], sm[t + o]);
        __syncthreads();
    }
    float gmax = sm[0];
    __syncthreads();
    float s = 0.f;
    for (int i = t; i < nb; i += 1024) s += g_red[i * 2 + 1] * expf(g_red[i * 2] - gmax);
    sm[t] = s;
    __syncthreads();
    for (int o = 512; o; o >>= 1) {
        if (t < o) sm[t] += sm[t + o];
        __syncthreads();
    }
    if (t == 0) { g_scalar[0] = gmax; g_scalar[1] = sm[0]; }
}

__global__ void final_kernel(const float* __restrict__ H,
                             const float* __restrict__ fW,
                             const float* __restrict__ fb,
                             float* __restrict__ out, int n) {
    int gw = (blockIdx.x * blockDim.x + threadIdx.x) >> 5;
    int lane = threadIdx.x & 31;
    if (gw >= n) return;
    float v = H[(size_t)gw * 64 + lane] * fW[lane] +
              H[(size_t)gw * 64 + lane + 32] * fW[lane + 32];
#pragma unroll
    for (int o = 16; o; o >>= 1) v += __shfl_xor_sync(0xFFFFFFFFu, v, o);
    if (lane == 0) {
        float attn = expf(g_a[gw] - g_scalar[0]) / g_scalar[1];
        float z = attn * v + fb[0];
        out[gw] = 1.f / (1.f + expf(-z));
        out[n + gw] = attn;
    }
}

// ---------------- launch ----------------
extern "C" void kernel_launch(void* const* d_in, const int* in_sizes, int n_in,
                              void* d_out, int out_size) {
    const float* x   = (const float*)d_in[0];
    const int*   ei  = (const int*)d_in[1];
    const float* W1  = (const float*)d_in[2];
    const float* b1  = (const float*)d_in[3];
    const float* W2  = (const float*)d_in[4];
    const float* b2  = (const float*)d_in[5];
    const float* W3  = (const float*)d_in[6];
    const float* b3  = (const float*)d_in[7];
    const float* aW  = (const float*)d_in[8];
    const float* ab  = (const float*)d_in[9];
    const float* fW  = (const float*)d_in[10];
    const float* fb  = (const float*)d_in[11];
    float* out = (float*)d_out;

    int N = in_sizes[0] / 128;
    int E = in_sizes[1] / 2;
    const int* src = ei;
    const int* dst = ei + E;

    __nv_bfloat16 *tb, *hb, *w1t, *w2t, *w3t;
    float* h3;
    int* deg_ptr;
    cudaGetSymbolAddress((void**)&tb, g_tb);
    cudaGetSymbolAddress((void**)&hb, g_hb);
    cudaGetSymbolAddress((void**)&h3, g_h);
    cudaGetSymbolAddress((void**)&deg_ptr, g_deg);
    cudaGetSymbolAddress((void**)&w1t, g_w1t);
    cudaGetSymbolAddress((void**)&w2t, g_w2t);
    cudaGetSymbolAddress((void**)&w3t, g_w3t);

    const int SM128 = 128 * LDW * 2;
    const int SM64  = 64 * LDW * 2;
    cudaFuncSetAttribute((const void*)mma_gemm_kernel<128, float>,
                         cudaFuncAttributeMaxDynamicSharedMemorySize, SM128);
    cudaFuncSetAttribute((const void*)mma_gemm_kernel<128, __nv_bfloat16>,
                         cudaFuncAttributeMaxDynamicSharedMemorySize, SM128);
    cudaFuncSetAttribute((const void*)mma_gemm_kernel<64, __nv_bfloat16>,
                         cudaFuncAttributeMaxDynamicSharedMemorySize, SM64);

    cudaMemsetAsync(deg_ptr, 0, (size_t)N * sizeof(int));
    prep_count_kernel<<<PREP_B + (E + 255) / 256, 256>>>(W1, W2, W3, dst, E);
    int nb = (N + SCAN_B - 1) / SCAN_B;
    scan1_kernel<<<nb, 256>>>(N, E);
    scan3_kernel<<<nb, 256>>>(N);
    fill_kernel<<<(E + 255) / 256, 256>>>(src, dst, E);

    int warpGrid = (N * 32 + 255) / 256;
    int mmaGrid = (N + 127) / 128;

    mma_gemm_kernel<128, float><<<mmaGrid, 256, SM128>>>(x, w1t, tb, N);
    agg128_kernel<<<warpGrid, 256>>>(tb, b1, hb, N);
    mma_gemm_kernel<128, __nv_bfloat16><<<mmaGrid, 256, SM128>>>(hb, w2t, tb, N);
    agg128_kernel<<<warpGrid, 256>>>(tb, b2, hb, N);
    mma_gemm_kernel<64, __nv_bfloat16><<<mmaGrid, 256, SM64>>>(hb, w3t, tb, N);
    agg3_attn_kernel<<<warpGrid, 256>>>(tb, b3, aW, ab, h3, N);

    combine_kernel<<<1, 1024>>>(warpGrid);
    final_kernel<<<warpGrid, 256>>>(h3, fW, fb, out, N);
}